// round 14
// baseline (speedup 1.0000x reference)
#include <cuda_runtime.h>
#include <cuda_bf16.h>
#include <cstdint>

// Problem constants (reference: N=100000, E=1000000, D=64)
#define MAXN 100000
#define MAXE 1000000
#define DIMF 64

// Scratch (device globals; no allocation allowed)
__device__ float g_agg[MAXN * DIMF];
__device__ float g_h1[MAXN * DIMF];
__device__ float g_h2[MAXN * DIMF];
__device__ int   g_cnt[MAXN];
__device__ int   g_rowptr[MAXN + 1];
__device__ int   g_cursor[MAXN];
__device__ int2  g_edata[MAXE];          // {src, float_bits(w)} grouped by dst
__device__ int   g_bsum[512];

// ---------------------------------------------------------------------------
// TF32 helpers
// ---------------------------------------------------------------------------
__device__ __forceinline__ uint32_t f2tf(float a) {
    uint32_t r; asm("cvt.rna.tf32.f32 %0, %1;" : "=r"(r) : "f"(a)); return r;
}
__device__ __forceinline__ void tf_split(float a, uint32_t& hi, uint32_t& lo) {
    hi = f2tf(a);
    lo = f2tf(a - __uint_as_float(hi));
}
__device__ __forceinline__ void mma_tf32(float c[4],
                                         uint32_t a0, uint32_t a1, uint32_t a2, uint32_t a3,
                                         uint32_t b0, uint32_t b1) {
    asm volatile(
        "mma.sync.aligned.m16n8k8.row.col.f32.tf32.tf32.f32 "
        "{%0,%1,%2,%3}, {%4,%5,%6,%7}, {%8,%9}, {%0,%1,%2,%3};"
        : "+f"(c[0]), "+f"(c[1]), "+f"(c[2]), "+f"(c[3])
        : "r"(a0), "r"(a1), "r"(a2), "r"(a3), "r"(b0), "r"(b1));
}

// ---------------------------------------------------------------------------
// CSR build: histogram -> exclusive scan -> fill
// ---------------------------------------------------------------------------
__global__ void zero_cnt_kernel(int* __restrict__ cnt, int N) {
    int i = blockIdx.x * blockDim.x + threadIdx.x;
    if (i < N) cnt[i] = 0;
}

__global__ void hist_kernel(const int* __restrict__ dst, int* __restrict__ cnt, int E) {
    int e = blockIdx.x * blockDim.x + threadIdx.x;
    if (e < E) atomicAdd(&cnt[dst[e]], 1);
}

__global__ void scan_partial_kernel(const int* __restrict__ cnt, int* __restrict__ bsum, int N) {
    __shared__ int sm[256];
    int i = blockIdx.x * 256 + threadIdx.x;
    sm[threadIdx.x] = (i < N) ? cnt[i] : 0;
    __syncthreads();
    for (int s = 128; s > 0; s >>= 1) {
        if (threadIdx.x < s) sm[threadIdx.x] += sm[threadIdx.x + s];
        __syncthreads();
    }
    if (threadIdx.x == 0) bsum[blockIdx.x] = sm[0];
}

// Single-block 512-thread exclusive scan (NB <= 512): one load wave,
// warp shfl scans + smem warp-sum scan, one store wave. Replaces the
// serial 13-iteration single-warp loop (latency-bound at ~5-6us).
__global__ void scan_top_kernel(int* __restrict__ bsum, int NB) {
    __shared__ int wsum[16];
    int t    = threadIdx.x;
    int lane = t & 31;
    int w    = t >> 5;
    int v = (t < NB) ? bsum[t] : 0;
    int s = v;
    #pragma unroll
    for (int d = 1; d < 32; d <<= 1) {
        int u = __shfl_up_sync(0xFFFFFFFFu, s, d);
        if (lane >= d) s += u;
    }
    if (lane == 31) wsum[w] = s;
    __syncthreads();
    if (w == 0 && lane < 16) {
        int ws = wsum[lane];
        #pragma unroll
        for (int d = 1; d < 16; d <<= 1) {
            int u = __shfl_up_sync(0xFFFFu, ws, d);
            if (lane >= d) ws += u;
        }
        wsum[lane] = ws;
    }
    __syncthreads();
    int off = (w > 0) ? wsum[w - 1] : 0;
    if (t < NB) bsum[t] = off + s - v;   // exclusive
}

__global__ void scan_final_kernel(const int* __restrict__ cnt,
                                  const int* __restrict__ bsum,
                                  int* __restrict__ rowptr,
                                  int* __restrict__ cursor, int N) {
    __shared__ int sm[256];
    int t = threadIdx.x;
    int i = blockIdx.x * 256 + t;
    int v = (i < N) ? cnt[i] : 0;
    sm[t] = v;
    __syncthreads();
    for (int s = 1; s < 256; s <<= 1) {
        int add = (t >= s) ? sm[t - s] : 0;
        __syncthreads();
        sm[t] += add;
        __syncthreads();
    }
    int val = bsum[blockIdx.x] + sm[t] - v;   // exclusive prefix
    if (i < N) {
        rowptr[i] = val;
        cursor[i] = val;
    } else if (i == N) {
        rowptr[N] = val;                      // == E
    }
}

__global__ void fill_kernel(const int* __restrict__ src, const int* __restrict__ dst,
                            const float* __restrict__ ew,
                            int* __restrict__ cursor, int2* __restrict__ edata, int E) {
    int e = blockIdx.x * blockDim.x + threadIdx.x;
    if (e >= E) return;
    int d = dst[e];
    int p = atomicAdd(&cursor[d], 1);
    edata[p] = make_int2(src[e], __float_as_int(ew[e]));
}

// ---------------------------------------------------------------------------
// Gather-aggregate: agg[n] = x[n] + sum_{e in csr(n)} x[src_e] * w_e
// (unchanged R6/R7 winner)
// ---------------------------------------------------------------------------
__global__ void gather_kernel(const float4* __restrict__ x4,
                              const int* __restrict__ rowptr,
                              const int2* __restrict__ edata,
                              float4* __restrict__ agg, int N) {
    int idx = blockIdx.x * blockDim.x + threadIdx.x;
    int n = idx >> 4;
    if (n >= N) return;
    int c = idx & 15;
    unsigned gmask = 0xFFFFu << (threadIdx.x & 16);   // this 16-lane group

    int beg = __ldg(rowptr + n);
    int end = __ldg(rowptr + n + 1);
    float4 acc = x4[(size_t)n * 16 + c];    // GIN identity term

    for (int base = beg; base < end; base += 16) {
        int e = base + c;
        int2 ed = (e < end) ? __ldg(edata + e) : make_int2(0, 0);
        #pragma unroll
        for (int i = 0; i < 16; i++) {
            int s   = __shfl_sync(gmask, ed.x, i, 16);
            float w = __int_as_float(__shfl_sync(gmask, ed.y, i, 16));
            float4 v = __ldg(&x4[(size_t)s * 16 + c]);
            acc.x += v.x * w; acc.y += v.y * w;
            acc.z += v.z * w; acc.w += v.w * w;
        }
    }
    agg[(size_t)n * 16 + c] = acc;
}

// ---------------------------------------------------------------------------
// TF32 MLP for H=64, TR=128 (R13 winner, unchanged).
// ---------------------------------------------------------------------------
template<bool RELU_OUT>
__global__ void __launch_bounds__(256, 2) mlp_tc64w_kernel(
        const float4* __restrict__ agg4,
        const float* __restrict__ w1, const float* __restrict__ b1,
        const float* __restrict__ w2, const float* __restrict__ b2,
        float* __restrict__ out, int N) {
    constexpr int TR  = 128;
    constexpr int INS = 68;         // ==4 mod 32
    constexpr int WS  = 72;         // ==8 mod 32
    constexpr int IN_SZ = TR * INS;
    constexpr int W_SZ  = 64 * WS;

    extern __shared__ float sm[];
    float* in_s = sm;
    float* w1n  = sm + IN_SZ;
    float* hid  = sm;                      // overlays in_s
    float* w2n  = w1n + W_SZ;
    float* b1s  = w2n + W_SZ;
    float* b2s  = b1s + 64;

    int tid  = threadIdx.x;
    int row0 = blockIdx.x * TR;
    int nrows = N - row0; if (nrows > TR) nrows = TR;

    for (int i = tid; i < 64 * 64; i += 256) {
        int k = i >> 6, n = i & 63;
        w1n[k * WS + n] = w1[i];
        w2n[k * WS + n] = w2[i];
    }
    if (tid < 64) b1s[tid] = b1[tid];
    else if (tid < 128) b2s[tid - 64] = b2[tid - 64];

    for (int i = tid; i < TR * 16; i += 256) {
        int r = i >> 4, k4 = i & 15;
        float4 v = make_float4(0.f, 0.f, 0.f, 0.f);
        if (r < nrows) v = agg4[(size_t)(row0 + r) * 16 + k4];
        *(float4*)(in_s + r * INS + k4 * 4) = v;
    }
    __syncthreads();

    const int wid  = tid >> 5;
    const int lane = tid & 31;
    const int g    = lane >> 2;
    const int tg   = lane & 3;
    const int m0   = wid * 16;

    float c1[8][4];
    #pragma unroll
    for (int j = 0; j < 8; j++) {
        int n0 = j * 8;
        float bv0 = b1s[n0 + 2 * tg], bv1 = b1s[n0 + 2 * tg + 1];
        c1[j][0] = bv0; c1[j][1] = bv1; c1[j][2] = bv0; c1[j][3] = bv1;
    }
    #pragma unroll
    for (int kk = 0; kk < 8; kk++) {
        int k0 = kk * 8;
        uint32_t ah[4], al[4];
        tf_split(in_s[(m0 + g)     * INS + k0 + tg],     ah[0], al[0]);
        tf_split(in_s[(m0 + g + 8) * INS + k0 + tg],     ah[1], al[1]);
        tf_split(in_s[(m0 + g)     * INS + k0 + tg + 4], ah[2], al[2]);
        tf_split(in_s[(m0 + g + 8) * INS + k0 + tg + 4], ah[3], al[3]);
        #pragma unroll
        for (int j = 0; j < 8; j++) {
            int n0 = j * 8;
            uint32_t bh0, bl0, bh1, bl1;
            tf_split(w1n[(k0 + tg)     * WS + n0 + g], bh0, bl0);
            tf_split(w1n[(k0 + tg + 4) * WS + n0 + g], bh1, bl1);
            mma_tf32(c1[j], ah[0], ah[1], ah[2], ah[3], bh0, bh1);
            mma_tf32(c1[j], ah[0], ah[1], ah[2], ah[3], bl0, bl1);
            mma_tf32(c1[j], al[0], al[1], al[2], al[3], bh0, bh1);
        }
    }
    __syncthreads();

    #pragma unroll
    for (int j = 0; j < 8; j++) {
        int n0 = j * 8 + 2 * tg;
        *(float2*)(hid + (m0 + g)     * INS + n0) =
            make_float2(fmaxf(c1[j][0], 0.f), fmaxf(c1[j][1], 0.f));
        *(float2*)(hid + (m0 + g + 8) * INS + n0) =
            make_float2(fmaxf(c1[j][2], 0.f), fmaxf(c1[j][3], 0.f));
    }
    __syncthreads();

    {
        float c2[8][4];
        #pragma unroll
        for (int j = 0; j < 8; j++) {
            int n0 = j * 8;
            float bv0 = b2s[n0 + 2 * tg], bv1 = b2s[n0 + 2 * tg + 1];
            c2[j][0] = bv0; c2[j][1] = bv1; c2[j][2] = bv0; c2[j][3] = bv1;
        }
        #pragma unroll
        for (int kk = 0; kk < 8; kk++) {
            int k0 = kk * 8;
            uint32_t ah[4], al[4];
            tf_split(hid[(m0 + g)     * INS + k0 + tg],     ah[0], al[0]);
            tf_split(hid[(m0 + g + 8) * INS + k0 + tg],     ah[1], al[1]);
            tf_split(hid[(m0 + g)     * INS + k0 + tg + 4], ah[2], al[2]);
            tf_split(hid[(m0 + g + 8) * INS + k0 + tg + 4], ah[3], al[3]);
            #pragma unroll
            for (int j = 0; j < 8; j++) {
                int n0 = j * 8;
                uint32_t bh0, bl0, bh1, bl1;
                tf_split(w2n[(k0 + tg)     * WS + n0 + g], bh0, bl0);
                tf_split(w2n[(k0 + tg + 4) * WS + n0 + g], bh1, bl1);
                mma_tf32(c2[j], ah[0], ah[1], ah[2], ah[3], bh0, bh1);
                mma_tf32(c2[j], ah[0], ah[1], ah[2], ah[3], bl0, bl1);
                mma_tf32(c2[j], al[0], al[1], al[2], al[3], bh0, bh1);
            }
        }
        int r0 = m0 + g, r1 = m0 + g + 8;
        #pragma unroll
        for (int j = 0; j < 8; j++) {
            int n0 = j * 8 + 2 * tg;
            if (r0 < nrows) {
                float2 v = make_float2(c2[j][0], c2[j][1]);
                if (RELU_OUT) { v.x = fmaxf(v.x, 0.f); v.y = fmaxf(v.y, 0.f); }
                *(float2*)(out + (size_t)(row0 + r0) * 64 + n0) = v;
            }
            if (r1 < nrows) {
                float2 v = make_float2(c2[j][2], c2[j][3]);
                if (RELU_OUT) { v.x = fmaxf(v.x, 0.f); v.y = fmaxf(v.y, 0.f); }
                *(float2*)(out + (size_t)(row0 + r1) * 64 + n0) = v;
            }
        }
    }
}

// ---------------------------------------------------------------------------
// TF32 MLP for H=128, TR=128 (NEW): 256 threads, 8 warps = 8 m-tiles, each
// warp covers full n (GEMM1 n=128 -> 16 tiles, c1=64 regs; GEMM2 n=64 -> 8).
// Smem 107.3KB -> 2 blocks/SM. hid[128][132] overlays in_s+w1n (16896 <=
// 17408 floats). Same fragment mapping / split math as all passing kernels.
// ---------------------------------------------------------------------------
template<bool RELU_OUT>
__global__ void __launch_bounds__(256, 2) mlp_tc128w_kernel(
        const float4* __restrict__ agg4,
        const float* __restrict__ w1, const float* __restrict__ b1,
        const float* __restrict__ w2, const float* __restrict__ b2,
        float* __restrict__ out, int N) {
    constexpr int TR  = 128;
    constexpr int H   = 128;
    constexpr int INS = 68;         // ==4 mod 32
    constexpr int W1S = H + 8;      // 136 ==8 mod 32
    constexpr int HS  = H + 4;      // 132 ==4 mod 32
    constexpr int W2S = 72;         // ==8 mod 32
    constexpr int IN_SZ = TR * INS; // 8704
    constexpr int W1_SZ = 64 * W1S; // 8704

    extern __shared__ float sm[];
    float* in_s = sm;                          // [128][68]
    float* w1n  = sm + IN_SZ;                  // [64][136]
    float* hid  = sm;                          // [128][132] overlays in+w1
    float* w2n  = sm + IN_SZ + W1_SZ;          // [128][72]
    float* b1s  = w2n + H * W2S;               // 128
    float* b2s  = b1s + H;                     // 64
    static_assert(TR * HS <= IN_SZ + W1_SZ, "hid overlay must fit");

    int tid  = threadIdx.x;
    int row0 = blockIdx.x * TR;
    int nrows = N - row0; if (nrows > TR) nrows = TR;

    for (int i = tid; i < 64 * H; i += 256) {
        int k = i / H, n = i % H;
        w1n[k * W1S + n] = w1[i];
    }
    for (int i = tid; i < H * 64; i += 256) {
        int h = i / 64, n = i % 64;
        w2n[h * W2S + n] = w2[i];
    }
    if (tid < H)  b1s[tid] = b1[tid];
    if (tid < 64) b2s[tid] = b2[tid];

    for (int i = tid; i < TR * 16; i += 256) {
        int r = i >> 4, k4 = i & 15;
        float4 v = make_float4(0.f, 0.f, 0.f, 0.f);
        if (r < nrows) v = agg4[(size_t)(row0 + r) * 16 + k4];
        *(float4*)(in_s + r * INS + k4 * 4) = v;
    }
    __syncthreads();

    const int wid  = tid >> 5;
    const int lane = tid & 31;
    const int g    = lane >> 2;
    const int tg   = lane & 3;
    const int m0   = wid * 16;      // 8 warps x 16 rows

    // ---- GEMM1: hid = relu(in @ W1 + b1), n = 128 (16 tiles/warp) ----
    float c1[16][4];
    #pragma unroll
    for (int j = 0; j < 16; j++) {
        int n0 = j * 8;
        float bv0 = b1s[n0 + 2 * tg], bv1 = b1s[n0 + 2 * tg + 1];
        c1[j][0] = bv0; c1[j][1] = bv1; c1[j][2] = bv0; c1[j][3] = bv1;
    }
    #pragma unroll
    for (int kk = 0; kk < 8; kk++) {        // K = 64
        int k0 = kk * 8;
        uint32_t ah[4], al[4];
        tf_split(in_s[(m0 + g)     * INS + k0 + tg],     ah[0], al[0]);
        tf_split(in_s[(m0 + g + 8) * INS + k0 + tg],     ah[1], al[1]);
        tf_split(in_s[(m0 + g)     * INS + k0 + tg + 4], ah[2], al[2]);
        tf_split(in_s[(m0 + g + 8) * INS + k0 + tg + 4], ah[3], al[3]);
        #pragma unroll
        for (int j = 0; j < 16; j++) {
            int n0 = j * 8;
            uint32_t bh0, bl0, bh1, bl1;
            tf_split(w1n[(k0 + tg)     * W1S + n0 + g], bh0, bl0);
            tf_split(w1n[(k0 + tg + 4) * W1S + n0 + g], bh1, bl1);
            mma_tf32(c1[j], ah[0], ah[1], ah[2], ah[3], bh0, bh1);
            mma_tf32(c1[j], ah[0], ah[1], ah[2], ah[3], bl0, bl1);
            mma_tf32(c1[j], al[0], al[1], al[2], al[3], bh0, bh1);
        }
    }
    __syncthreads();   // all reads of in_s / w1n done

    // Write relu(hid) (overlays in_s+w1n)
    #pragma unroll
    for (int j = 0; j < 16; j++) {
        int n0 = j * 8 + 2 * tg;
        *(float2*)(hid + (m0 + g)     * HS + n0) =
            make_float2(fmaxf(c1[j][0], 0.f), fmaxf(c1[j][1], 0.f));
        *(float2*)(hid + (m0 + g + 8) * HS + n0) =
            make_float2(fmaxf(c1[j][2], 0.f), fmaxf(c1[j][3], 0.f));
    }
    __syncthreads();

    // ---- GEMM2: out = hid @ W2 + b2, K = 128, n = 64 (8 tiles/warp) ----
    {
        float c2[8][4];
        #pragma unroll
        for (int j = 0; j < 8; j++) {
            int n0 = j * 8;
            float bv0 = b2s[n0 + 2 * tg], bv1 = b2s[n0 + 2 * tg + 1];
            c2[j][0] = bv0; c2[j][1] = bv1; c2[j][2] = bv0; c2[j][3] = bv1;
        }
        #pragma unroll
        for (int kk = 0; kk < 16; kk++) {   // K = 128
            int k0 = kk * 8;
            uint32_t ah[4], al[4];
            tf_split(hid[(m0 + g)     * HS + k0 + tg],     ah[0], al[0]);
            tf_split(hid[(m0 + g + 8) * HS + k0 + tg],     ah[1], al[1]);
            tf_split(hid[(m0 + g)     * HS + k0 + tg + 4], ah[2], al[2]);
            tf_split(hid[(m0 + g + 8) * HS + k0 + tg + 4], ah[3], al[3]);
            #pragma unroll
            for (int j = 0; j < 8; j++) {
                int n0 = j * 8;
                uint32_t bh0, bl0, bh1, bl1;
                tf_split(w2n[(k0 + tg)     * W2S + n0 + g], bh0, bl0);
                tf_split(w2n[(k0 + tg + 4) * W2S + n0 + g], bh1, bl1);
                mma_tf32(c2[j], ah[0], ah[1], ah[2], ah[3], bh0, bh1);
                mma_tf32(c2[j], ah[0], ah[1], ah[2], ah[3], bl0, bl1);
                mma_tf32(c2[j], al[0], al[1], al[2], al[3], bh0, bh1);
            }
        }
        int r0 = m0 + g, r1 = m0 + g + 8;
        #pragma unroll
        for (int j = 0; j < 8; j++) {
            int n0 = j * 8 + 2 * tg;
            if (r0 < nrows) {
                float2 v = make_float2(c2[j][0], c2[j][1]);
                if (RELU_OUT) { v.x = fmaxf(v.x, 0.f); v.y = fmaxf(v.y, 0.f); }
                *(float2*)(out + (size_t)(row0 + r0) * 64 + n0) = v;
            }
            if (r1 < nrows) {
                float2 v = make_float2(c2[j][2], c2[j][3]);
                if (RELU_OUT) { v.x = fmaxf(v.x, 0.f); v.y = fmaxf(v.y, 0.f); }
                *(float2*)(out + (size_t)(row0 + r1) * 64 + n0) = v;
            }
        }
    }
}

// ---------------------------------------------------------------------------
// Launch
// ---------------------------------------------------------------------------
static inline size_t smem_tc64w() {
    return (size_t)(128 * 68 + 2 * 64 * 72 + 128) * sizeof(float);
}
static inline size_t smem_tc128w() {
    // in(128*68) + w1(64*136) + w2(128*72) + b1(128) + b2(64)
    return (size_t)(128 * 68 + 64 * 136 + 128 * 72 + 128 + 64) * sizeof(float);
}

extern "C" void kernel_launch(void* const* d_in, const int* in_sizes, int n_in,
                              void* d_out, int out_size) {
    const float* x   = (const float*)d_in[0];
    const int*   ei  = (const int*)d_in[1];
    const float* ew  = (const float*)d_in[2];
    const float* w11 = (const float*)d_in[3];
    const float* b11 = (const float*)d_in[4];
    const float* w12 = (const float*)d_in[5];
    const float* b12 = (const float*)d_in[6];
    const float* w21 = (const float*)d_in[7];
    const float* b21 = (const float*)d_in[8];
    const float* w22 = (const float*)d_in[9];
    const float* b22 = (const float*)d_in[10];
    const float* w31 = (const float*)d_in[11];
    const float* b31 = (const float*)d_in[12];
    const float* w32 = (const float*)d_in[13];
    const float* b32 = (const float*)d_in[14];
    float* out = (float*)d_out;

    int N = in_sizes[0] / DIMF;
    int E = in_sizes[1] / 2;
    const int* src = ei;
    const int* dst = ei + E;

    float *agg, *h1, *h2;
    int *cnt, *rowptr, *cursor, *bsum;
    int2 *edata;
    cudaGetSymbolAddress((void**)&agg, g_agg);
    cudaGetSymbolAddress((void**)&h1, g_h1);
    cudaGetSymbolAddress((void**)&h2, g_h2);
    cudaGetSymbolAddress((void**)&cnt, g_cnt);
    cudaGetSymbolAddress((void**)&rowptr, g_rowptr);
    cudaGetSymbolAddress((void**)&cursor, g_cursor);
    cudaGetSymbolAddress((void**)&bsum, g_bsum);
    cudaGetSymbolAddress((void**)&edata, g_edata);

    size_t smW   = smem_tc64w();
    size_t smW2  = smem_tc128w();
    cudaFuncSetAttribute(mlp_tc64w_kernel<true>,   cudaFuncAttributeMaxDynamicSharedMemorySize, (int)smW);
    cudaFuncSetAttribute(mlp_tc64w_kernel<false>,  cudaFuncAttributeMaxDynamicSharedMemorySize, (int)smW);
    cudaFuncSetAttribute(mlp_tc128w_kernel<true>,  cudaFuncAttributeMaxDynamicSharedMemorySize, (int)smW2);

    int NB = (N + 255) / 256;                // scan blocks (<=512 required)
    int eb = (E + 255) / 256;
    int gb = (N * 16 + 255) / 256;
    int mb = (N + 127) / 128;

    // --- CSR build (by destination) ---
    zero_cnt_kernel<<<NB, 256>>>(cnt, N);
    hist_kernel<<<eb, 256>>>(dst, cnt, E);
    scan_partial_kernel<<<NB, 256>>>(cnt, bsum, N);
    scan_top_kernel<<<1, 512>>>(bsum, NB);
    scan_final_kernel<<<NB + 1, 256>>>(cnt, bsum, rowptr, cursor, N);
    fill_kernel<<<eb, 256>>>(src, dst, ew, cursor, edata, E);

    // --- Layer 1: 64 -> 64 -> 64, relu ---
    gather_kernel<<<gb, 256>>>((const float4*)x, rowptr, edata, (float4*)agg, N);
    mlp_tc64w_kernel<true><<<mb, 256, smW>>>((const float4*)agg, w11, b11, w12, b12, h1, N);

    // --- Layer 2: 64 -> 128 -> 64, relu (TR=128) ---
    gather_kernel<<<gb, 256>>>((const float4*)h1, rowptr, edata, (float4*)agg, N);
    mlp_tc128w_kernel<true><<<mb, 256, smW2>>>((const float4*)agg, w21, b21, w22, b22, h2, N);

    // --- Layer 3: 64 -> 64 -> 64, no relu ---
    gather_kernel<<<gb, 256>>>((const float4*)h2, rowptr, edata, (float4*)agg, N);
    mlp_tc64w_kernel<false><<<mb, 256, smW>>>((const float4*)agg, w31, b31, w32, b32, out, N);
}

// round 15
// speedup vs baseline: 1.4620x; 1.4620x over previous
#include <cuda_runtime.h>
#include <cuda_bf16.h>
#include <cstdint>

// Problem constants (reference: N=100000, E=1000000, D=64)
#define MAXN 100000
#define MAXE 1000000
#define DIMF 64

// Scratch (device globals; no allocation allowed)
__device__ float g_agg[MAXN * DIMF];
__device__ float g_h1[MAXN * DIMF];
__device__ float g_h2[MAXN * DIMF];
__device__ int   g_cnt[MAXN];
__device__ int   g_rowptr[MAXN + 1];
__device__ int   g_cursor[MAXN];
__device__ int2  g_edata[MAXE];          // {src, float_bits(w)} grouped by dst
__device__ int   g_bsum[512];

// ---------------------------------------------------------------------------
// TF32 helpers
// ---------------------------------------------------------------------------
__device__ __forceinline__ uint32_t f2tf(float a) {
    uint32_t r; asm("cvt.rna.tf32.f32 %0, %1;" : "=r"(r) : "f"(a)); return r;
}
__device__ __forceinline__ void tf_split(float a, uint32_t& hi, uint32_t& lo) {
    hi = f2tf(a);
    lo = f2tf(a - __uint_as_float(hi));
}
__device__ __forceinline__ void mma_tf32(float c[4],
                                         uint32_t a0, uint32_t a1, uint32_t a2, uint32_t a3,
                                         uint32_t b0, uint32_t b1) {
    asm volatile(
        "mma.sync.aligned.m16n8k8.row.col.f32.tf32.tf32.f32 "
        "{%0,%1,%2,%3}, {%4,%5,%6,%7}, {%8,%9}, {%0,%1,%2,%3};"
        : "+f"(c[0]), "+f"(c[1]), "+f"(c[2]), "+f"(c[3])
        : "r"(a0), "r"(a1), "r"(a2), "r"(a3), "r"(b0), "r"(b1));
}

// ---------------------------------------------------------------------------
// CSR build: histogram -> exclusive scan -> fill
// ---------------------------------------------------------------------------
__global__ void zero_cnt_kernel(int* __restrict__ cnt, int N) {
    int i = blockIdx.x * blockDim.x + threadIdx.x;
    if (i < N) cnt[i] = 0;
}

__global__ void hist_kernel(const int* __restrict__ dst, int* __restrict__ cnt, int E) {
    int e = blockIdx.x * blockDim.x + threadIdx.x;
    if (e < E) atomicAdd(&cnt[dst[e]], 1);
}

__global__ void scan_partial_kernel(const int* __restrict__ cnt, int* __restrict__ bsum, int N) {
    __shared__ int sm[256];
    int i = blockIdx.x * 256 + threadIdx.x;
    sm[threadIdx.x] = (i < N) ? cnt[i] : 0;
    __syncthreads();
    for (int s = 128; s > 0; s >>= 1) {
        if (threadIdx.x < s) sm[threadIdx.x] += sm[threadIdx.x + s];
        __syncthreads();
    }
    if (threadIdx.x == 0) bsum[blockIdx.x] = sm[0];
}

// Single-block 512-thread exclusive scan (NB <= 512)
__global__ void scan_top_kernel(int* __restrict__ bsum, int NB) {
    __shared__ int wsum[16];
    int t    = threadIdx.x;
    int lane = t & 31;
    int w    = t >> 5;
    int v = (t < NB) ? bsum[t] : 0;
    int s = v;
    #pragma unroll
    for (int d = 1; d < 32; d <<= 1) {
        int u = __shfl_up_sync(0xFFFFFFFFu, s, d);
        if (lane >= d) s += u;
    }
    if (lane == 31) wsum[w] = s;
    __syncthreads();
    if (w == 0 && lane < 16) {
        int ws = wsum[lane];
        #pragma unroll
        for (int d = 1; d < 16; d <<= 1) {
            int u = __shfl_up_sync(0xFFFFu, ws, d);
            if (lane >= d) ws += u;
        }
        wsum[lane] = ws;
    }
    __syncthreads();
    int off = (w > 0) ? wsum[w - 1] : 0;
    if (t < NB) bsum[t] = off + s - v;   // exclusive
}

__global__ void scan_final_kernel(const int* __restrict__ cnt,
                                  const int* __restrict__ bsum,
                                  int* __restrict__ rowptr,
                                  int* __restrict__ cursor, int N) {
    __shared__ int sm[256];
    int t = threadIdx.x;
    int i = blockIdx.x * 256 + t;
    int v = (i < N) ? cnt[i] : 0;
    sm[t] = v;
    __syncthreads();
    for (int s = 1; s < 256; s <<= 1) {
        int add = (t >= s) ? sm[t - s] : 0;
        __syncthreads();
        sm[t] += add;
        __syncthreads();
    }
    int val = bsum[blockIdx.x] + sm[t] - v;   // exclusive prefix
    if (i < N) {
        rowptr[i] = val;
        cursor[i] = val;
    } else if (i == N) {
        rowptr[N] = val;                      // == E
    }
}

__global__ void fill_kernel(const int* __restrict__ src, const int* __restrict__ dst,
                            const float* __restrict__ ew,
                            int* __restrict__ cursor, int2* __restrict__ edata, int E) {
    int e = blockIdx.x * blockDim.x + threadIdx.x;
    if (e >= E) return;
    int d = dst[e];
    int p = atomicAdd(&cursor[d], 1);
    edata[p] = make_int2(src[e], __float_as_int(ew[e]));
}

// ---------------------------------------------------------------------------
// Gather-aggregate: agg[n] = x[n] + sum_{e in csr(n)} x[src_e] * w_e
// (unchanged R6/R7 winner)
// ---------------------------------------------------------------------------
__global__ void gather_kernel(const float4* __restrict__ x4,
                              const int* __restrict__ rowptr,
                              const int2* __restrict__ edata,
                              float4* __restrict__ agg, int N) {
    int idx = blockIdx.x * blockDim.x + threadIdx.x;
    int n = idx >> 4;
    if (n >= N) return;
    int c = idx & 15;
    unsigned gmask = 0xFFFFu << (threadIdx.x & 16);   // this 16-lane group

    int beg = __ldg(rowptr + n);
    int end = __ldg(rowptr + n + 1);
    float4 acc = x4[(size_t)n * 16 + c];    // GIN identity term

    for (int base = beg; base < end; base += 16) {
        int e = base + c;
        int2 ed = (e < end) ? __ldg(edata + e) : make_int2(0, 0);
        #pragma unroll
        for (int i = 0; i < 16; i++) {
            int s   = __shfl_sync(gmask, ed.x, i, 16);
            float w = __int_as_float(__shfl_sync(gmask, ed.y, i, 16));
            float4 v = __ldg(&x4[(size_t)s * 16 + c]);
            acc.x += v.x * w; acc.y += v.y * w;
            acc.z += v.z * w; acc.w += v.w * w;
        }
    }
    agg[(size_t)n * 16 + c] = acc;
}

// ---------------------------------------------------------------------------
// TF32 MLP for H=64, TR=128 (R13 winner, unchanged).
// ---------------------------------------------------------------------------
template<bool RELU_OUT>
__global__ void __launch_bounds__(256, 2) mlp_tc64w_kernel(
        const float4* __restrict__ agg4,
        const float* __restrict__ w1, const float* __restrict__ b1,
        const float* __restrict__ w2, const float* __restrict__ b2,
        float* __restrict__ out, int N) {
    constexpr int TR  = 128;
    constexpr int INS = 68;         // ==4 mod 32
    constexpr int WS  = 72;         // ==8 mod 32
    constexpr int IN_SZ = TR * INS;
    constexpr int W_SZ  = 64 * WS;

    extern __shared__ float sm[];
    float* in_s = sm;
    float* w1n  = sm + IN_SZ;
    float* hid  = sm;                      // overlays in_s
    float* w2n  = w1n + W_SZ;
    float* b1s  = w2n + W_SZ;
    float* b2s  = b1s + 64;

    int tid  = threadIdx.x;
    int row0 = blockIdx.x * TR;
    int nrows = N - row0; if (nrows > TR) nrows = TR;

    for (int i = tid; i < 64 * 64; i += 256) {
        int k = i >> 6, n = i & 63;
        w1n[k * WS + n] = w1[i];
        w2n[k * WS + n] = w2[i];
    }
    if (tid < 64) b1s[tid] = b1[tid];
    else if (tid < 128) b2s[tid - 64] = b2[tid - 64];

    for (int i = tid; i < TR * 16; i += 256) {
        int r = i >> 4, k4 = i & 15;
        float4 v = make_float4(0.f, 0.f, 0.f, 0.f);
        if (r < nrows) v = agg4[(size_t)(row0 + r) * 16 + k4];
        *(float4*)(in_s + r * INS + k4 * 4) = v;
    }
    __syncthreads();

    const int wid  = tid >> 5;
    const int lane = tid & 31;
    const int g    = lane >> 2;
    const int tg   = lane & 3;
    const int m0   = wid * 16;

    float c1[8][4];
    #pragma unroll
    for (int j = 0; j < 8; j++) {
        int n0 = j * 8;
        float bv0 = b1s[n0 + 2 * tg], bv1 = b1s[n0 + 2 * tg + 1];
        c1[j][0] = bv0; c1[j][1] = bv1; c1[j][2] = bv0; c1[j][3] = bv1;
    }
    #pragma unroll
    for (int kk = 0; kk < 8; kk++) {
        int k0 = kk * 8;
        uint32_t ah[4], al[4];
        tf_split(in_s[(m0 + g)     * INS + k0 + tg],     ah[0], al[0]);
        tf_split(in_s[(m0 + g + 8) * INS + k0 + tg],     ah[1], al[1]);
        tf_split(in_s[(m0 + g)     * INS + k0 + tg + 4], ah[2], al[2]);
        tf_split(in_s[(m0 + g + 8) * INS + k0 + tg + 4], ah[3], al[3]);
        #pragma unroll
        for (int j = 0; j < 8; j++) {
            int n0 = j * 8;
            uint32_t bh0, bl0, bh1, bl1;
            tf_split(w1n[(k0 + tg)     * WS + n0 + g], bh0, bl0);
            tf_split(w1n[(k0 + tg + 4) * WS + n0 + g], bh1, bl1);
            mma_tf32(c1[j], ah[0], ah[1], ah[2], ah[3], bh0, bh1);
            mma_tf32(c1[j], ah[0], ah[1], ah[2], ah[3], bl0, bl1);
            mma_tf32(c1[j], al[0], al[1], al[2], al[3], bh0, bh1);
        }
    }
    __syncthreads();

    #pragma unroll
    for (int j = 0; j < 8; j++) {
        int n0 = j * 8 + 2 * tg;
        *(float2*)(hid + (m0 + g)     * INS + n0) =
            make_float2(fmaxf(c1[j][0], 0.f), fmaxf(c1[j][1], 0.f));
        *(float2*)(hid + (m0 + g + 8) * INS + n0) =
            make_float2(fmaxf(c1[j][2], 0.f), fmaxf(c1[j][3], 0.f));
    }
    __syncthreads();

    {
        float c2[8][4];
        #pragma unroll
        for (int j = 0; j < 8; j++) {
            int n0 = j * 8;
            float bv0 = b2s[n0 + 2 * tg], bv1 = b2s[n0 + 2 * tg + 1];
            c2[j][0] = bv0; c2[j][1] = bv1; c2[j][2] = bv0; c2[j][3] = bv1;
        }
        #pragma unroll
        for (int kk = 0; kk < 8; kk++) {
            int k0 = kk * 8;
            uint32_t ah[4], al[4];
            tf_split(hid[(m0 + g)     * INS + k0 + tg],     ah[0], al[0]);
            tf_split(hid[(m0 + g + 8) * INS + k0 + tg],     ah[1], al[1]);
            tf_split(hid[(m0 + g)     * INS + k0 + tg + 4], ah[2], al[2]);
            tf_split(hid[(m0 + g + 8) * INS + k0 + tg + 4], ah[3], al[3]);
            #pragma unroll
            for (int j = 0; j < 8; j++) {
                int n0 = j * 8;
                uint32_t bh0, bl0, bh1, bl1;
                tf_split(w2n[(k0 + tg)     * WS + n0 + g], bh0, bl0);
                tf_split(w2n[(k0 + tg + 4) * WS + n0 + g], bh1, bl1);
                mma_tf32(c2[j], ah[0], ah[1], ah[2], ah[3], bh0, bh1);
                mma_tf32(c2[j], ah[0], ah[1], ah[2], ah[3], bl0, bl1);
                mma_tf32(c2[j], al[0], al[1], al[2], al[3], bh0, bh1);
            }
        }
        int r0 = m0 + g, r1 = m0 + g + 8;
        #pragma unroll
        for (int j = 0; j < 8; j++) {
            int n0 = j * 8 + 2 * tg;
            if (r0 < nrows) {
                float2 v = make_float2(c2[j][0], c2[j][1]);
                if (RELU_OUT) { v.x = fmaxf(v.x, 0.f); v.y = fmaxf(v.y, 0.f); }
                *(float2*)(out + (size_t)(row0 + r0) * 64 + n0) = v;
            }
            if (r1 < nrows) {
                float2 v = make_float2(c2[j][2], c2[j][3]);
                if (RELU_OUT) { v.x = fmaxf(v.x, 0.f); v.y = fmaxf(v.y, 0.f); }
                *(float2*)(out + (size_t)(row0 + r1) * 64 + n0) = v;
            }
        }
    }
}

// ---------------------------------------------------------------------------
// On-the-fly split TF32 MLP, TR=64 (R10 winner, byte-for-byte) -- H=128.
// ---------------------------------------------------------------------------
template<int H, bool RELU_OUT>
__global__ void __launch_bounds__(256, 2) mlp_tc_kernel(
        const float4* __restrict__ agg4,
        const float* __restrict__ w1, const float* __restrict__ b1,
        const float* __restrict__ w2, const float* __restrict__ b2,
        float* __restrict__ out, int N) {
    constexpr int TR   = 64;
    constexpr int INS  = 68;
    constexpr int W1S  = H + 8;
    constexpr int HS   = H + 4;
    constexpr int W2S  = 72;
    constexpr int IN_SZ = TR * INS;
    constexpr int W1_SZ = 64 * W1S;
    constexpr int NT1  = H / 16;
    constexpr int KS2  = H / 8;

    extern __shared__ float sm[];
    float* in_s = sm;
    float* w1n  = sm + IN_SZ;
    float* hid  = sm;
    float* w2n  = sm + IN_SZ + W1_SZ;
    float* b1s  = w2n + H * W2S;
    float* b2s  = b1s + H;
    static_assert(TR * HS <= IN_SZ + W1_SZ, "hid overlay must fit");

    int tid  = threadIdx.x;
    int row0 = blockIdx.x * TR;
    int nrows = N - row0; if (nrows > TR) nrows = TR;

    for (int i = tid; i < 64 * H; i += 256) {
        int k = i / H, n = i % H;
        w1n[k * W1S + n] = w1[i];
    }
    for (int i = tid; i < H * 64; i += 256) {
        int h = i / 64, n = i % 64;
        w2n[h * W2S + n] = w2[i];
    }
    if (tid < H)  b1s[tid] = b1[tid];
    if (tid < 64) b2s[tid] = b2[tid];

    for (int i = tid; i < TR * 16; i += 256) {
        int r = i >> 4, k4 = i & 15;
        float4 v = make_float4(0.f, 0.f, 0.f, 0.f);
        if (r < nrows) v = agg4[(size_t)(row0 + r) * 16 + k4];
        *(float4*)(in_s + r * INS + k4 * 4) = v;
    }
    __syncthreads();

    const int wid  = tid >> 5;
    const int lane = tid & 31;
    const int g    = lane >> 2;
    const int tg   = lane & 3;
    const int m0   = (wid >> 1) * 16;
    const int nb1  = (wid & 1) * NT1 * 8;

    float c1[NT1][4];
    #pragma unroll
    for (int j = 0; j < NT1; j++) {
        int n0 = nb1 + j * 8;
        float bv0 = b1s[n0 + 2 * tg], bv1 = b1s[n0 + 2 * tg + 1];
        c1[j][0] = bv0; c1[j][1] = bv1; c1[j][2] = bv0; c1[j][3] = bv1;
    }
    #pragma unroll
    for (int kk = 0; kk < 8; kk++) {
        int k0 = kk * 8;
        uint32_t ah[4], al[4];
        tf_split(in_s[(m0 + g)     * INS + k0 + tg],     ah[0], al[0]);
        tf_split(in_s[(m0 + g + 8) * INS + k0 + tg],     ah[1], al[1]);
        tf_split(in_s[(m0 + g)     * INS + k0 + tg + 4], ah[2], al[2]);
        tf_split(in_s[(m0 + g + 8) * INS + k0 + tg + 4], ah[3], al[3]);
        #pragma unroll
        for (int j = 0; j < NT1; j++) {
            int n0 = nb1 + j * 8;
            uint32_t bh0, bl0, bh1, bl1;
            tf_split(w1n[(k0 + tg)     * W1S + n0 + g], bh0, bl0);
            tf_split(w1n[(k0 + tg + 4) * W1S + n0 + g], bh1, bl1);
            mma_tf32(c1[j], ah[0], ah[1], ah[2], ah[3], bh0, bh1);
            mma_tf32(c1[j], ah[0], ah[1], ah[2], ah[3], bl0, bl1);
            mma_tf32(c1[j], al[0], al[1], al[2], al[3], bh0, bh1);
        }
    }
    __syncthreads();

    #pragma unroll
    for (int j = 0; j < NT1; j++) {
        int n0 = nb1 + j * 8 + 2 * tg;
        *(float2*)(hid + (m0 + g)     * HS + n0) =
            make_float2(fmaxf(c1[j][0], 0.f), fmaxf(c1[j][1], 0.f));
        *(float2*)(hid + (m0 + g + 8) * HS + n0) =
            make_float2(fmaxf(c1[j][2], 0.f), fmaxf(c1[j][3], 0.f));
    }
    __syncthreads();

    {
        constexpr int NT2 = 4;
        int nb2 = (wid & 1) * 32;
        float c2[NT2][4];
        #pragma unroll
        for (int j = 0; j < NT2; j++) {
            int n0 = nb2 + j * 8;
            float bv0 = b2s[n0 + 2 * tg], bv1 = b2s[n0 + 2 * tg + 1];
            c2[j][0] = bv0; c2[j][1] = bv1; c2[j][2] = bv0; c2[j][3] = bv1;
        }
        #pragma unroll
        for (int kk = 0; kk < KS2; kk++) {
            int k0 = kk * 8;
            uint32_t ah[4], al[4];
            tf_split(hid[(m0 + g)     * HS + k0 + tg],     ah[0], al[0]);
            tf_split(hid[(m0 + g + 8) * HS + k0 + tg],     ah[1], al[1]);
            tf_split(hid[(m0 + g)     * HS + k0 + tg + 4], ah[2], al[2]);
            tf_split(hid[(m0 + g + 8) * HS + k0 + tg + 4], ah[3], al[3]);
            #pragma unroll
            for (int j = 0; j < NT2; j++) {
                int n0 = nb2 + j * 8;
                uint32_t bh0, bl0, bh1, bl1;
                tf_split(w2n[(k0 + tg)     * W2S + n0 + g], bh0, bl0);
                tf_split(w2n[(k0 + tg + 4) * W2S + n0 + g], bh1, bl1);
                mma_tf32(c2[j], ah[0], ah[1], ah[2], ah[3], bh0, bh1);
                mma_tf32(c2[j], ah[0], ah[1], ah[2], ah[3], bl0, bl1);
                mma_tf32(c2[j], al[0], al[1], al[2], al[3], bh0, bh1);
            }
        }
        int r0 = m0 + g, r1 = m0 + g + 8;
        #pragma unroll
        for (int j = 0; j < NT2; j++) {
            int n0 = nb2 + j * 8 + 2 * tg;
            if (r0 < nrows) {
                float2 v = make_float2(c2[j][0], c2[j][1]);
                if (RELU_OUT) { v.x = fmaxf(v.x, 0.f); v.y = fmaxf(v.y, 0.f); }
                *(float2*)(out + (size_t)(row0 + r0) * 64 + n0) = v;
            }
            if (r1 < nrows) {
                float2 v = make_float2(c2[j][2], c2[j][3]);
                if (RELU_OUT) { v.x = fmaxf(v.x, 0.f); v.y = fmaxf(v.y, 0.f); }
                *(float2*)(out + (size_t)(row0 + r1) * 64 + n0) = v;
            }
        }
    }
}

// ---------------------------------------------------------------------------
// Launch
// ---------------------------------------------------------------------------
static inline size_t smem_tc64w() {
    return (size_t)(128 * 68 + 2 * 64 * 72 + 128) * sizeof(float);
}
static inline size_t smem_otf(int H) {
    size_t floats = (size_t)64 * 68 + (size_t)64 * (H + 8) + (size_t)H * 72 + H + 64;
    return floats * sizeof(float);
}

extern "C" void kernel_launch(void* const* d_in, const int* in_sizes, int n_in,
                              void* d_out, int out_size) {
    const float* x   = (const float*)d_in[0];
    const int*   ei  = (const int*)d_in[1];
    const float* ew  = (const float*)d_in[2];
    const float* w11 = (const float*)d_in[3];
    const float* b11 = (const float*)d_in[4];
    const float* w12 = (const float*)d_in[5];
    const float* b12 = (const float*)d_in[6];
    const float* w21 = (const float*)d_in[7];
    const float* b21 = (const float*)d_in[8];
    const float* w22 = (const float*)d_in[9];
    const float* b22 = (const float*)d_in[10];
    const float* w31 = (const float*)d_in[11];
    const float* b31 = (const float*)d_in[12];
    const float* w32 = (const float*)d_in[13];
    const float* b32 = (const float*)d_in[14];
    float* out = (float*)d_out;

    int N = in_sizes[0] / DIMF;
    int E = in_sizes[1] / 2;
    const int* src = ei;
    const int* dst = ei + E;

    float *agg, *h1, *h2;
    int *cnt, *rowptr, *cursor, *bsum;
    int2 *edata;
    cudaGetSymbolAddress((void**)&agg, g_agg);
    cudaGetSymbolAddress((void**)&h1, g_h1);
    cudaGetSymbolAddress((void**)&h2, g_h2);
    cudaGetSymbolAddress((void**)&cnt, g_cnt);
    cudaGetSymbolAddress((void**)&rowptr, g_rowptr);
    cudaGetSymbolAddress((void**)&cursor, g_cursor);
    cudaGetSymbolAddress((void**)&bsum, g_bsum);
    cudaGetSymbolAddress((void**)&edata, g_edata);

    size_t smW   = smem_tc64w();
    size_t sm128 = smem_otf(128);
    cudaFuncSetAttribute(mlp_tc64w_kernel<true>,   cudaFuncAttributeMaxDynamicSharedMemorySize, (int)smW);
    cudaFuncSetAttribute(mlp_tc64w_kernel<false>,  cudaFuncAttributeMaxDynamicSharedMemorySize, (int)smW);
    cudaFuncSetAttribute(mlp_tc_kernel<128, true>, cudaFuncAttributeMaxDynamicSharedMemorySize, (int)sm128);

    int NB = (N + 255) / 256;                // scan blocks (<=512 required)
    int eb = (E + 255) / 256;
    int gb = (N * 16 + 255) / 256;
    int mb64  = (N + 127) / 128;
    int mb128 = (N + 63) / 64;

    // --- CSR build (by destination) ---
    zero_cnt_kernel<<<NB, 256>>>(cnt, N);
    hist_kernel<<<eb, 256>>>(dst, cnt, E);
    scan_partial_kernel<<<NB, 256>>>(cnt, bsum, N);
    scan_top_kernel<<<1, 512>>>(bsum, NB);
    scan_final_kernel<<<NB + 1, 256>>>(cnt, bsum, rowptr, cursor, N);
    fill_kernel<<<eb, 256>>>(src, dst, ew, cursor, edata, E);

    // --- Layer 1: 64 -> 64 -> 64, relu (TR=128) ---
    gather_kernel<<<gb, 256>>>((const float4*)x, rowptr, edata, (float4*)agg, N);
    mlp_tc64w_kernel<true><<<mb64, 256, smW>>>((const float4*)agg, w11, b11, w12, b12, h1, N);

    // --- Layer 2: 64 -> 128 -> 64, relu (R10 kernel, TR=64) ---
    gather_kernel<<<gb, 256>>>((const float4*)h1, rowptr, edata, (float4*)agg, N);
    mlp_tc_kernel<128, true><<<mb128, 256, sm128>>>((const float4*)agg, w21, b21, w22, b22, h2, N);

    // --- Layer 3: 64 -> 64 -> 64, no relu (TR=128) ---
    gather_kernel<<<gb, 256>>>((const float4*)h2, rowptr, edata, (float4*)agg, N);
    mlp_tc64w_kernel<false><<<mb64, 256, smW>>>((const float4*)agg, w31, b31, w32, b32, out, N);
}

// round 16
// speedup vs baseline: 1.5669x; 1.0717x over previous
#include <cuda_runtime.h>
#include <cuda_bf16.h>
#include <cstdint>

// Problem constants (reference: N=100000, E=1000000, D=64)
#define MAXN 100000
#define MAXE 1000000
#define DIMF 64

// Scratch (device globals; no allocation allowed)
__device__ float g_agg[MAXN * DIMF];
__device__ float g_h1[MAXN * DIMF];
__device__ float g_h2[MAXN * DIMF];
__device__ int   g_cnt[MAXN];
__device__ int   g_rowptr[MAXN + 1];
__device__ int   g_cursor[MAXN];
__device__ int2  g_edata[MAXE];          // {src, float_bits(w)} grouped by dst
__device__ int   g_bsum[512];

// ---------------------------------------------------------------------------
// TF32 helpers (layer-2 kernel)
// ---------------------------------------------------------------------------
__device__ __forceinline__ uint32_t f2tf(float a) {
    uint32_t r; asm("cvt.rna.tf32.f32 %0, %1;" : "=r"(r) : "f"(a)); return r;
}
__device__ __forceinline__ void tf_split(float a, uint32_t& hi, uint32_t& lo) {
    hi = f2tf(a);
    lo = f2tf(a - __uint_as_float(hi));
}
__device__ __forceinline__ void mma_tf32(float c[4],
                                         uint32_t a0, uint32_t a1, uint32_t a2, uint32_t a3,
                                         uint32_t b0, uint32_t b1) {
    asm volatile(
        "mma.sync.aligned.m16n8k8.row.col.f32.tf32.tf32.f32 "
        "{%0,%1,%2,%3}, {%4,%5,%6,%7}, {%8,%9}, {%0,%1,%2,%3};"
        : "+f"(c[0]), "+f"(c[1]), "+f"(c[2]), "+f"(c[3])
        : "r"(a0), "r"(a1), "r"(a2), "r"(a3), "r"(b0), "r"(b1));
}

// ---------------------------------------------------------------------------
// BF16-split helpers (H=64 layers): a = hi(bf16) + lo(bf16), hi exact via shift
// ---------------------------------------------------------------------------
__device__ __forceinline__ void bf_split2(float2 p, uint32_t& hi, uint32_t& lo) {
    asm("cvt.rn.bf16x2.f32 %0, %1, %2;" : "=r"(hi) : "f"(p.y), "f"(p.x));
    float fx = __uint_as_float(hi << 16);            // exact fp32 of bf16(p.x)
    float fy = __uint_as_float(hi & 0xFFFF0000u);    // exact fp32 of bf16(p.y)
    asm("cvt.rn.bf16x2.f32 %0, %1, %2;" : "=r"(lo) : "f"(p.y - fy), "f"(p.x - fx));
}
__device__ __forceinline__ void mma_bf16(float c[4],
                                         uint32_t a0, uint32_t a1, uint32_t a2, uint32_t a3,
                                         uint32_t b0, uint32_t b1) {
    asm volatile(
        "mma.sync.aligned.m16n8k16.row.col.f32.bf16.bf16.f32 "
        "{%0,%1,%2,%3}, {%4,%5,%6,%7}, {%8,%9}, {%0,%1,%2,%3};"
        : "+f"(c[0]), "+f"(c[1]), "+f"(c[2]), "+f"(c[3])
        : "r"(a0), "r"(a1), "r"(a2), "r"(a3), "r"(b0), "r"(b1));
}

// ---------------------------------------------------------------------------
// CSR build: histogram -> exclusive scan -> fill
// ---------------------------------------------------------------------------
__global__ void zero_cnt_kernel(int* __restrict__ cnt, int N) {
    int i = blockIdx.x * blockDim.x + threadIdx.x;
    if (i < N) cnt[i] = 0;
}

__global__ void hist_kernel(const int* __restrict__ dst, int* __restrict__ cnt, int E) {
    int e = blockIdx.x * blockDim.x + threadIdx.x;
    if (e < E) atomicAdd(&cnt[dst[e]], 1);
}

__global__ void scan_partial_kernel(const int* __restrict__ cnt, int* __restrict__ bsum, int N) {
    __shared__ int sm[256];
    int i = blockIdx.x * 256 + threadIdx.x;
    sm[threadIdx.x] = (i < N) ? cnt[i] : 0;
    __syncthreads();
    for (int s = 128; s > 0; s >>= 1) {
        if (threadIdx.x < s) sm[threadIdx.x] += sm[threadIdx.x + s];
        __syncthreads();
    }
    if (threadIdx.x == 0) bsum[blockIdx.x] = sm[0];
}

// Single-block 512-thread exclusive scan (NB <= 512)
__global__ void scan_top_kernel(int* __restrict__ bsum, int NB) {
    __shared__ int wsum[16];
    int t    = threadIdx.x;
    int lane = t & 31;
    int w    = t >> 5;
    int v = (t < NB) ? bsum[t] : 0;
    int s = v;
    #pragma unroll
    for (int d = 1; d < 32; d <<= 1) {
        int u = __shfl_up_sync(0xFFFFFFFFu, s, d);
        if (lane >= d) s += u;
    }
    if (lane == 31) wsum[w] = s;
    __syncthreads();
    if (w == 0 && lane < 16) {
        int ws = wsum[lane];
        #pragma unroll
        for (int d = 1; d < 16; d <<= 1) {
            int u = __shfl_up_sync(0xFFFFu, ws, d);
            if (lane >= d) ws += u;
        }
        wsum[lane] = ws;
    }
    __syncthreads();
    int off = (w > 0) ? wsum[w - 1] : 0;
    if (t < NB) bsum[t] = off + s - v;   // exclusive
}

__global__ void scan_final_kernel(const int* __restrict__ cnt,
                                  const int* __restrict__ bsum,
                                  int* __restrict__ rowptr,
                                  int* __restrict__ cursor, int N) {
    __shared__ int sm[256];
    int t = threadIdx.x;
    int i = blockIdx.x * 256 + t;
    int v = (i < N) ? cnt[i] : 0;
    sm[t] = v;
    __syncthreads();
    for (int s = 1; s < 256; s <<= 1) {
        int add = (t >= s) ? sm[t - s] : 0;
        __syncthreads();
        sm[t] += add;
        __syncthreads();
    }
    int val = bsum[blockIdx.x] + sm[t] - v;   // exclusive prefix
    if (i < N) {
        rowptr[i] = val;
        cursor[i] = val;
    } else if (i == N) {
        rowptr[N] = val;                      // == E
    }
}

__global__ void fill_kernel(const int* __restrict__ src, const int* __restrict__ dst,
                            const float* __restrict__ ew,
                            int* __restrict__ cursor, int2* __restrict__ edata, int E) {
    int e = blockIdx.x * blockDim.x + threadIdx.x;
    if (e >= E) return;
    int d = dst[e];
    int p = atomicAdd(&cursor[d], 1);
    edata[p] = make_int2(src[e], __float_as_int(ew[e]));
}

// ---------------------------------------------------------------------------
// Gather-aggregate: agg[n] = x[n] + sum_{e in csr(n)} x[src_e] * w_e
// (unchanged R6/R7 winner)
// ---------------------------------------------------------------------------
__global__ void gather_kernel(const float4* __restrict__ x4,
                              const int* __restrict__ rowptr,
                              const int2* __restrict__ edata,
                              float4* __restrict__ agg, int N) {
    int idx = blockIdx.x * blockDim.x + threadIdx.x;
    int n = idx >> 4;
    if (n >= N) return;
    int c = idx & 15;
    unsigned gmask = 0xFFFFu << (threadIdx.x & 16);   // this 16-lane group

    int beg = __ldg(rowptr + n);
    int end = __ldg(rowptr + n + 1);
    float4 acc = x4[(size_t)n * 16 + c];    // GIN identity term

    for (int base = beg; base < end; base += 16) {
        int e = base + c;
        int2 ed = (e < end) ? __ldg(edata + e) : make_int2(0, 0);
        #pragma unroll
        for (int i = 0; i < 16; i++) {
            int s   = __shfl_sync(gmask, ed.x, i, 16);
            float w = __int_as_float(__shfl_sync(gmask, ed.y, i, 16));
            float4 v = __ldg(&x4[(size_t)s * 16 + c]);
            acc.x += v.x * w; acc.y += v.y * w;
            acc.z += v.z * w; acc.w += v.w * w;
        }
    }
    agg[(size_t)n * 16 + c] = acc;
}

// ---------------------------------------------------------------------------
// BF16-split MLP for H=64, TR=128 (256 threads, 2 blocks/SM; smem 74.2KB).
// m16n8k16 bf16 MMAs: a = hi+lo (bf16), D += Ah*Bh + Ah*Bl + Al*Bh, fp32
// accumulate -> half the MMA count of the tf32 k8 version.
// in_s/hid stride 72 (==8 mod 32): float2 pair-loads are optimal 2-phase.
// Weights staged TRANSPOSED w?t[n][k] stride 72 so B k-pairs are aligned
// float2 (staging-store conflicts are one-time, amortized).
// C-fragment layout identical to tf32 version -> epilogue unchanged.
// ---------------------------------------------------------------------------
template<bool RELU_OUT>
__global__ void __launch_bounds__(256, 2) mlp_bf64_kernel(
        const float4* __restrict__ agg4,
        const float* __restrict__ w1, const float* __restrict__ b1,
        const float* __restrict__ w2, const float* __restrict__ b2,
        float* __restrict__ out, int N) {
    constexpr int TR  = 128;
    constexpr int S   = 72;         // stride (floats), ==8 mod 32
    constexpr int IN_SZ = TR * S;   // 9216
    constexpr int W_SZ  = 64 * S;   // 4608

    extern __shared__ float sm[];
    float* in_s = sm;                      // [128][72] activations
    float* w1t  = sm + IN_SZ;              // [64][72]  w1 transposed [n][k]
    float* hid  = sm;                      // [128][72] overlays in_s
    float* w2t  = w1t + W_SZ;              // [64][72]  w2 transposed [n][k]
    float* b1s  = w2t + W_SZ;              // 64
    float* b2s  = b1s + 64;                // 64

    int tid  = threadIdx.x;
    int row0 = blockIdx.x * TR;
    int nrows = N - row0; if (nrows > TR) nrows = TR;

    // Stage weights transposed: w?t[n*S + k] = w?[k*64 + n]
    for (int i = tid; i < 64 * 64; i += 256) {
        int k = i >> 6, n = i & 63;
        w1t[n * S + k] = w1[i];
        w2t[n * S + k] = w2[i];
    }
    if (tid < 64) b1s[tid] = b1[tid];
    else if (tid < 128) b2s[tid - 64] = b2[tid - 64];

    // Stage input tile (zero-pad tail rows)
    for (int i = tid; i < TR * 16; i += 256) {
        int r = i >> 4, k4 = i & 15;
        float4 v = make_float4(0.f, 0.f, 0.f, 0.f);
        if (r < nrows) v = agg4[(size_t)(row0 + r) * 16 + k4];
        *(float4*)(in_s + r * S + k4 * 4) = v;
    }
    __syncthreads();

    const int wid  = tid >> 5;
    const int lane = tid & 31;
    const int g    = lane >> 2;
    const int tg   = lane & 3;
    const int m0   = wid * 16;      // 8 warps x 16 rows = 128

    // ---- GEMM1: hid = relu(in @ W1 + b1), K=64 (4 k16-steps) ----
    float c1[8][4];
    #pragma unroll
    for (int j = 0; j < 8; j++) {
        int n0 = j * 8;
        float bv0 = b1s[n0 + 2 * tg], bv1 = b1s[n0 + 2 * tg + 1];
        c1[j][0] = bv0; c1[j][1] = bv1; c1[j][2] = bv0; c1[j][3] = bv1;
    }
    #pragma unroll
    for (int kk = 0; kk < 4; kk++) {
        int k0 = kk * 16;
        // A fragments: rows m0+g, m0+g+8; k pairs at k0+2tg and k0+2tg+8
        uint32_t ah[4], al[4];
        bf_split2(*(const float2*)(in_s + (m0 + g)     * S + k0 + 2 * tg),     ah[0], al[0]);
        bf_split2(*(const float2*)(in_s + (m0 + g + 8) * S + k0 + 2 * tg),     ah[1], al[1]);
        bf_split2(*(const float2*)(in_s + (m0 + g)     * S + k0 + 8 + 2 * tg), ah[2], al[2]);
        bf_split2(*(const float2*)(in_s + (m0 + g + 8) * S + k0 + 8 + 2 * tg), ah[3], al[3]);
        #pragma unroll
        for (int j = 0; j < 8; j++) {
            int n0 = j * 8;
            uint32_t bh0, bl0, bh1, bl1;
            bf_split2(*(const float2*)(w1t + (n0 + g) * S + k0 + 2 * tg),     bh0, bl0);
            bf_split2(*(const float2*)(w1t + (n0 + g) * S + k0 + 8 + 2 * tg), bh1, bl1);
            mma_bf16(c1[j], ah[0], ah[1], ah[2], ah[3], bh0, bh1);
            mma_bf16(c1[j], ah[0], ah[1], ah[2], ah[3], bl0, bl1);
            mma_bf16(c1[j], al[0], al[1], al[2], al[3], bh0, bh1);
        }
    }
    __syncthreads();   // all reads of in_s done

    // Write relu(hid) (overlays in_s; stride S, float2 offsets even)
    #pragma unroll
    for (int j = 0; j < 8; j++) {
        int n0 = j * 8 + 2 * tg;
        *(float2*)(hid + (m0 + g)     * S + n0) =
            make_float2(fmaxf(c1[j][0], 0.f), fmaxf(c1[j][1], 0.f));
        *(float2*)(hid + (m0 + g + 8) * S + n0) =
            make_float2(fmaxf(c1[j][2], 0.f), fmaxf(c1[j][3], 0.f));
    }
    __syncthreads();

    // ---- GEMM2: out = hid @ W2 + b2, K=64 ----
    {
        float c2[8][4];
        #pragma unroll
        for (int j = 0; j < 8; j++) {
            int n0 = j * 8;
            float bv0 = b2s[n0 + 2 * tg], bv1 = b2s[n0 + 2 * tg + 1];
            c2[j][0] = bv0; c2[j][1] = bv1; c2[j][2] = bv0; c2[j][3] = bv1;
        }
        #pragma unroll
        for (int kk = 0; kk < 4; kk++) {
            int k0 = kk * 16;
            uint32_t ah[4], al[4];
            bf_split2(*(const float2*)(hid + (m0 + g)     * S + k0 + 2 * tg),     ah[0], al[0]);
            bf_split2(*(const float2*)(hid + (m0 + g + 8) * S + k0 + 2 * tg),     ah[1], al[1]);
            bf_split2(*(const float2*)(hid + (m0 + g)     * S + k0 + 8 + 2 * tg), ah[2], al[2]);
            bf_split2(*(const float2*)(hid + (m0 + g + 8) * S + k0 + 8 + 2 * tg), ah[3], al[3]);
            #pragma unroll
            for (int j = 0; j < 8; j++) {
                int n0 = j * 8;
                uint32_t bh0, bl0, bh1, bl1;
                bf_split2(*(const float2*)(w2t + (n0 + g) * S + k0 + 2 * tg),     bh0, bl0);
                bf_split2(*(const float2*)(w2t + (n0 + g) * S + k0 + 8 + 2 * tg), bh1, bl1);
                mma_bf16(c2[j], ah[0], ah[1], ah[2], ah[3], bh0, bh1);
                mma_bf16(c2[j], ah[0], ah[1], ah[2], ah[3], bl0, bl1);
                mma_bf16(c2[j], al[0], al[1], al[2], al[3], bh0, bh1);
            }
        }
        int r0 = m0 + g, r1 = m0 + g + 8;
        #pragma unroll
        for (int j = 0; j < 8; j++) {
            int n0 = j * 8 + 2 * tg;
            if (r0 < nrows) {
                float2 v = make_float2(c2[j][0], c2[j][1]);
                if (RELU_OUT) { v.x = fmaxf(v.x, 0.f); v.y = fmaxf(v.y, 0.f); }
                *(float2*)(out + (size_t)(row0 + r0) * 64 + n0) = v;
            }
            if (r1 < nrows) {
                float2 v = make_float2(c2[j][2], c2[j][3]);
                if (RELU_OUT) { v.x = fmaxf(v.x, 0.f); v.y = fmaxf(v.y, 0.f); }
                *(float2*)(out + (size_t)(row0 + r1) * 64 + n0) = v;
            }
        }
    }
}

// ---------------------------------------------------------------------------
// On-the-fly split TF32 MLP, TR=64 (R10 winner, byte-for-byte) -- H=128.
// ---------------------------------------------------------------------------
template<int H, bool RELU_OUT>
__global__ void __launch_bounds__(256, 2) mlp_tc_kernel(
        const float4* __restrict__ agg4,
        const float* __restrict__ w1, const float* __restrict__ b1,
        const float* __restrict__ w2, const float* __restrict__ b2,
        float* __restrict__ out, int N) {
    constexpr int TR   = 64;
    constexpr int INS  = 68;
    constexpr int W1S  = H + 8;
    constexpr int HS   = H + 4;
    constexpr int W2S  = 72;
    constexpr int IN_SZ = TR * INS;
    constexpr int W1_SZ = 64 * W1S;
    constexpr int NT1  = H / 16;
    constexpr int KS2  = H / 8;

    extern __shared__ float sm[];
    float* in_s = sm;
    float* w1n  = sm + IN_SZ;
    float* hid  = sm;
    float* w2n  = sm + IN_SZ + W1_SZ;
    float* b1s  = w2n + H * W2S;
    float* b2s  = b1s + H;
    static_assert(TR * HS <= IN_SZ + W1_SZ, "hid overlay must fit");

    int tid  = threadIdx.x;
    int row0 = blockIdx.x * TR;
    int nrows = N - row0; if (nrows > TR) nrows = TR;

    for (int i = tid; i < 64 * H; i += 256) {
        int k = i / H, n = i % H;
        w1n[k * W1S + n] = w1[i];
    }
    for (int i = tid; i < H * 64; i += 256) {
        int h = i / 64, n = i % 64;
        w2n[h * W2S + n] = w2[i];
    }
    if (tid < H)  b1s[tid] = b1[tid];
    if (tid < 64) b2s[tid] = b2[tid];

    for (int i = tid; i < TR * 16; i += 256) {
        int r = i >> 4, k4 = i & 15;
        float4 v = make_float4(0.f, 0.f, 0.f, 0.f);
        if (r < nrows) v = agg4[(size_t)(row0 + r) * 16 + k4];
        *(float4*)(in_s + r * INS + k4 * 4) = v;
    }
    __syncthreads();

    const int wid  = tid >> 5;
    const int lane = tid & 31;
    const int g    = lane >> 2;
    const int tg   = lane & 3;
    const int m0   = (wid >> 1) * 16;
    const int nb1  = (wid & 1) * NT1 * 8;

    float c1[NT1][4];
    #pragma unroll
    for (int j = 0; j < NT1; j++) {
        int n0 = nb1 + j * 8;
        float bv0 = b1s[n0 + 2 * tg], bv1 = b1s[n0 + 2 * tg + 1];
        c1[j][0] = bv0; c1[j][1] = bv1; c1[j][2] = bv0; c1[j][3] = bv1;
    }
    #pragma unroll
    for (int kk = 0; kk < 8; kk++) {
        int k0 = kk * 8;
        uint32_t ah[4], al[4];
        tf_split(in_s[(m0 + g)     * INS + k0 + tg],     ah[0], al[0]);
        tf_split(in_s[(m0 + g + 8) * INS + k0 + tg],     ah[1], al[1]);
        tf_split(in_s[(m0 + g)     * INS + k0 + tg + 4], ah[2], al[2]);
        tf_split(in_s[(m0 + g + 8) * INS + k0 + tg + 4], ah[3], al[3]);
        #pragma unroll
        for (int j = 0; j < NT1; j++) {
            int n0 = nb1 + j * 8;
            uint32_t bh0, bl0, bh1, bl1;
            tf_split(w1n[(k0 + tg)     * W1S + n0 + g], bh0, bl0);
            tf_split(w1n[(k0 + tg + 4) * W1S + n0 + g], bh1, bl1);
            mma_tf32(c1[j], ah[0], ah[1], ah[2], ah[3], bh0, bh1);
            mma_tf32(c1[j], ah[0], ah[1], ah[2], ah[3], bl0, bl1);
            mma_tf32(c1[j], al[0], al[1], al[2], al[3], bh0, bh1);
        }
    }
    __syncthreads();

    #pragma unroll
    for (int j = 0; j < NT1; j++) {
        int n0 = nb1 + j * 8 + 2 * tg;
        *(float2*)(hid + (m0 + g)     * HS + n0) =
            make_float2(fmaxf(c1[j][0], 0.f), fmaxf(c1[j][1], 0.f));
        *(float2*)(hid + (m0 + g + 8) * HS + n0) =
            make_float2(fmaxf(c1[j][2], 0.f), fmaxf(c1[j][3], 0.f));
    }
    __syncthreads();

    {
        constexpr int NT2 = 4;
        int nb2 = (wid & 1) * 32;
        float c2[NT2][4];
        #pragma unroll
        for (int j = 0; j < NT2; j++) {
            int n0 = nb2 + j * 8;
            float bv0 = b2s[n0 + 2 * tg], bv1 = b2s[n0 + 2 * tg + 1];
            c2[j][0] = bv0; c2[j][1] = bv1; c2[j][2] = bv0; c2[j][3] = bv1;
        }
        #pragma unroll
        for (int kk = 0; kk < KS2; kk++) {
            int k0 = kk * 8;
            uint32_t ah[4], al[4];
            tf_split(hid[(m0 + g)     * HS + k0 + tg],     ah[0], al[0]);
            tf_split(hid[(m0 + g + 8) * HS + k0 + tg],     ah[1], al[1]);
            tf_split(hid[(m0 + g)     * HS + k0 + tg + 4], ah[2], al[2]);
            tf_split(hid[(m0 + g + 8) * HS + k0 + tg + 4], ah[3], al[3]);
            #pragma unroll
            for (int j = 0; j < NT2; j++) {
                int n0 = nb2 + j * 8;
                uint32_t bh0, bl0, bh1, bl1;
                tf_split(w2n[(k0 + tg)     * W2S + n0 + g], bh0, bl0);
                tf_split(w2n[(k0 + tg + 4) * W2S + n0 + g], bh1, bl1);
                mma_tf32(c2[j], ah[0], ah[1], ah[2], ah[3], bh0, bh1);
                mma_tf32(c2[j], ah[0], ah[1], ah[2], ah[3], bl0, bl1);
                mma_tf32(c2[j], al[0], al[1], al[2], al[3], bh0, bh1);
            }
        }
        int r0 = m0 + g, r1 = m0 + g + 8;
        #pragma unroll
        for (int j = 0; j < NT2; j++) {
            int n0 = nb2 + j * 8 + 2 * tg;
            if (r0 < nrows) {
                float2 v = make_float2(c2[j][0], c2[j][1]);
                if (RELU_OUT) { v.x = fmaxf(v.x, 0.f); v.y = fmaxf(v.y, 0.f); }
                *(float2*)(out + (size_t)(row0 + r0) * 64 + n0) = v;
            }
            if (r1 < nrows) {
                float2 v = make_float2(c2[j][2], c2[j][3]);
                if (RELU_OUT) { v.x = fmaxf(v.x, 0.f); v.y = fmaxf(v.y, 0.f); }
                *(float2*)(out + (size_t)(row0 + r1) * 64 + n0) = v;
            }
        }
    }
}

// ---------------------------------------------------------------------------
// Launch
// ---------------------------------------------------------------------------
static inline size_t smem_bf64() {
    // in(128*72) + w1t(64*72) + w2t(64*72) + biases(128)
    return (size_t)(128 * 72 + 2 * 64 * 72 + 128) * sizeof(float);
}
static inline size_t smem_otf(int H) {
    size_t floats = (size_t)64 * 68 + (size_t)64 * (H + 8) + (size_t)H * 72 + H + 64;
    return floats * sizeof(float);
}

extern "C" void kernel_launch(void* const* d_in, const int* in_sizes, int n_in,
                              void* d_out, int out_size) {
    const float* x   = (const float*)d_in[0];
    const int*   ei  = (const int*)d_in[1];
    const float* ew  = (const float*)d_in[2];
    const float* w11 = (const float*)d_in[3];
    const float* b11 = (const float*)d_in[4];
    const float* w12 = (const float*)d_in[5];
    const float* b12 = (const float*)d_in[6];
    const float* w21 = (const float*)d_in[7];
    const float* b21 = (const float*)d_in[8];
    const float* w22 = (const float*)d_in[9];
    const float* b22 = (const float*)d_in[10];
    const float* w31 = (const float*)d_in[11];
    const float* b31 = (const float*)d_in[12];
    const float* w32 = (const float*)d_in[13];
    const float* b32 = (const float*)d_in[14];
    float* out = (float*)d_out;

    int N = in_sizes[0] / DIMF;
    int E = in_sizes[1] / 2;
    const int* src = ei;
    const int* dst = ei + E;

    float *agg, *h1, *h2;
    int *cnt, *rowptr, *cursor, *bsum;
    int2 *edata;
    cudaGetSymbolAddress((void**)&agg, g_agg);
    cudaGetSymbolAddress((void**)&h1, g_h1);
    cudaGetSymbolAddress((void**)&h2, g_h2);
    cudaGetSymbolAddress((void**)&cnt, g_cnt);
    cudaGetSymbolAddress((void**)&rowptr, g_rowptr);
    cudaGetSymbolAddress((void**)&cursor, g_cursor);
    cudaGetSymbolAddress((void**)&bsum, g_bsum);
    cudaGetSymbolAddress((void**)&edata, g_edata);

    size_t smB   = smem_bf64();
    size_t sm128 = smem_otf(128);
    cudaFuncSetAttribute(mlp_bf64_kernel<true>,   cudaFuncAttributeMaxDynamicSharedMemorySize, (int)smB);
    cudaFuncSetAttribute(mlp_bf64_kernel<false>,  cudaFuncAttributeMaxDynamicSharedMemorySize, (int)smB);
    cudaFuncSetAttribute(mlp_tc_kernel<128, true>, cudaFuncAttributeMaxDynamicSharedMemorySize, (int)sm128);

    int NB = (N + 255) / 256;                // scan blocks (<=512 required)
    int eb = (E + 255) / 256;
    int gb = (N * 16 + 255) / 256;
    int mb64  = (N + 127) / 128;
    int mb128 = (N + 63) / 64;

    // --- CSR build (by destination) ---
    zero_cnt_kernel<<<NB, 256>>>(cnt, N);
    hist_kernel<<<eb, 256>>>(dst, cnt, E);
    scan_partial_kernel<<<NB, 256>>>(cnt, bsum, N);
    scan_top_kernel<<<1, 512>>>(bsum, NB);
    scan_final_kernel<<<NB + 1, 256>>>(cnt, bsum, rowptr, cursor, N);
    fill_kernel<<<eb, 256>>>(src, dst, ew, cursor, edata, E);

    // --- Layer 1: 64 -> 64 -> 64, relu (bf16-split, TR=128) ---
    gather_kernel<<<gb, 256>>>((const float4*)x, rowptr, edata, (float4*)agg, N);
    mlp_bf64_kernel<true><<<mb64, 256, smB>>>((const float4*)agg, w11, b11, w12, b12, h1, N);

    // --- Layer 2: 64 -> 128 -> 64, relu (tf32 R10 kernel, TR=64) ---
    gather_kernel<<<gb, 256>>>((const float4*)h1, rowptr, edata, (float4*)agg, N);
    mlp_tc_kernel<128, true><<<mb128, 256, sm128>>>((const float4*)agg, w21, b21, w22, b22, h2, N);

    // --- Layer 3: 64 -> 64 -> 64, no relu (bf16-split, TR=128) ---
    gather_kernel<<<gb, 256>>>((const float4*)h2, rowptr, edata, (float4*)agg, N);
    mlp_bf64_kernel<false><<<mb64, 256, smB>>>((const float4*)agg, w31, b31, w32, b32, out, N);
}

// round 17
// speedup vs baseline: 1.6576x; 1.0579x over previous
#include <cuda_runtime.h>
#include <cuda_bf16.h>
#include <cstdint>

// Problem constants (reference: N=100000, E=1000000, D=64)
#define MAXN 100000
#define MAXE 1000000
#define DIMF 64

// Scratch (device globals; no allocation allowed)
__device__ float g_agg[MAXN * DIMF];
__device__ float g_h1[MAXN * DIMF];
__device__ float g_h2[MAXN * DIMF];
__device__ int   g_cnt[MAXN];
__device__ int   g_rowptr[MAXN + 1];
__device__ int   g_cursor[MAXN];
__device__ int2  g_edata[MAXE];          // {src, float_bits(w)} grouped by dst
__device__ int   g_bsum[512];

// ---------------------------------------------------------------------------
// BF16-split helpers: a = hi(bf16) + lo(bf16), hi extraction exact via bits
// ---------------------------------------------------------------------------
__device__ __forceinline__ void bf_split2(float2 p, uint32_t& hi, uint32_t& lo) {
    asm("cvt.rn.bf16x2.f32 %0, %1, %2;" : "=r"(hi) : "f"(p.y), "f"(p.x));
    float fx = __uint_as_float(hi << 16);            // exact fp32 of bf16(p.x)
    float fy = __uint_as_float(hi & 0xFFFF0000u);    // exact fp32 of bf16(p.y)
    asm("cvt.rn.bf16x2.f32 %0, %1, %2;" : "=r"(lo) : "f"(p.y - fy), "f"(p.x - fx));
}
__device__ __forceinline__ void mma_bf16(float c[4],
                                         uint32_t a0, uint32_t a1, uint32_t a2, uint32_t a3,
                                         uint32_t b0, uint32_t b1) {
    asm volatile(
        "mma.sync.aligned.m16n8k16.row.col.f32.bf16.bf16.f32 "
        "{%0,%1,%2,%3}, {%4,%5,%6,%7}, {%8,%9}, {%0,%1,%2,%3};"
        : "+f"(c[0]), "+f"(c[1]), "+f"(c[2]), "+f"(c[3])
        : "r"(a0), "r"(a1), "r"(a2), "r"(a3), "r"(b0), "r"(b1));
}

// ---------------------------------------------------------------------------
// CSR build: histogram -> exclusive scan -> fill
// ---------------------------------------------------------------------------
__global__ void zero_cnt_kernel(int* __restrict__ cnt, int N) {
    int i = blockIdx.x * blockDim.x + threadIdx.x;
    if (i < N) cnt[i] = 0;
}

__global__ void hist_kernel(const int* __restrict__ dst, int* __restrict__ cnt, int E) {
    int e = blockIdx.x * blockDim.x + threadIdx.x;
    if (e < E) atomicAdd(&cnt[dst[e]], 1);
}

__global__ void scan_partial_kernel(const int* __restrict__ cnt, int* __restrict__ bsum, int N) {
    __shared__ int sm[256];
    int i = blockIdx.x * 256 + threadIdx.x;
    sm[threadIdx.x] = (i < N) ? cnt[i] : 0;
    __syncthreads();
    for (int s = 128; s > 0; s >>= 1) {
        if (threadIdx.x < s) sm[threadIdx.x] += sm[threadIdx.x + s];
        __syncthreads();
    }
    if (threadIdx.x == 0) bsum[blockIdx.x] = sm[0];
}

// Single-block 512-thread exclusive scan (NB <= 512)
__global__ void scan_top_kernel(int* __restrict__ bsum, int NB) {
    __shared__ int wsum[16];
    int t    = threadIdx.x;
    int lane = t & 31;
    int w    = t >> 5;
    int v = (t < NB) ? bsum[t] : 0;
    int s = v;
    #pragma unroll
    for (int d = 1; d < 32; d <<= 1) {
        int u = __shfl_up_sync(0xFFFFFFFFu, s, d);
        if (lane >= d) s += u;
    }
    if (lane == 31) wsum[w] = s;
    __syncthreads();
    if (w == 0 && lane < 16) {
        int ws = wsum[lane];
        #pragma unroll
        for (int d = 1; d < 16; d <<= 1) {
            int u = __shfl_up_sync(0xFFFFu, ws, d);
            if (lane >= d) ws += u;
        }
        wsum[lane] = ws;
    }
    __syncthreads();
    int off = (w > 0) ? wsum[w - 1] : 0;
    if (t < NB) bsum[t] = off + s - v;   // exclusive
}

__global__ void scan_final_kernel(const int* __restrict__ cnt,
                                  const int* __restrict__ bsum,
                                  int* __restrict__ rowptr,
                                  int* __restrict__ cursor, int N) {
    __shared__ int sm[256];
    int t = threadIdx.x;
    int i = blockIdx.x * 256 + t;
    int v = (i < N) ? cnt[i] : 0;
    sm[t] = v;
    __syncthreads();
    for (int s = 1; s < 256; s <<= 1) {
        int add = (t >= s) ? sm[t - s] : 0;
        __syncthreads();
        sm[t] += add;
        __syncthreads();
    }
    int val = bsum[blockIdx.x] + sm[t] - v;   // exclusive prefix
    if (i < N) {
        rowptr[i] = val;
        cursor[i] = val;
    } else if (i == N) {
        rowptr[N] = val;                      // == E
    }
}

__global__ void fill_kernel(const int* __restrict__ src, const int* __restrict__ dst,
                            const float* __restrict__ ew,
                            int* __restrict__ cursor, int2* __restrict__ edata, int E) {
    int e = blockIdx.x * blockDim.x + threadIdx.x;
    if (e >= E) return;
    int d = dst[e];
    int p = atomicAdd(&cursor[d], 1);
    edata[p] = make_int2(src[e], __float_as_int(ew[e]));
}

// ---------------------------------------------------------------------------
// Gather-aggregate: agg[n] = x[n] + sum_{e in csr(n)} x[src_e] * w_e
// (unchanged R6/R7 winner)
// ---------------------------------------------------------------------------
__global__ void gather_kernel(const float4* __restrict__ x4,
                              const int* __restrict__ rowptr,
                              const int2* __restrict__ edata,
                              float4* __restrict__ agg, int N) {
    int idx = blockIdx.x * blockDim.x + threadIdx.x;
    int n = idx >> 4;
    if (n >= N) return;
    int c = idx & 15;
    unsigned gmask = 0xFFFFu << (threadIdx.x & 16);   // this 16-lane group

    int beg = __ldg(rowptr + n);
    int end = __ldg(rowptr + n + 1);
    float4 acc = x4[(size_t)n * 16 + c];    // GIN identity term

    for (int base = beg; base < end; base += 16) {
        int e = base + c;
        int2 ed = (e < end) ? __ldg(edata + e) : make_int2(0, 0);
        #pragma unroll
        for (int i = 0; i < 16; i++) {
            int s   = __shfl_sync(gmask, ed.x, i, 16);
            float w = __int_as_float(__shfl_sync(gmask, ed.y, i, 16));
            float4 v = __ldg(&x4[(size_t)s * 16 + c]);
            acc.x += v.x * w; acc.y += v.y * w;
            acc.z += v.z * w; acc.w += v.w * w;
        }
    }
    agg[(size_t)n * 16 + c] = acc;
}

// ---------------------------------------------------------------------------
// BF16-split MLP for H=64, TR=128 (R16 winner, unchanged).
// ---------------------------------------------------------------------------
template<bool RELU_OUT>
__global__ void __launch_bounds__(256, 2) mlp_bf64_kernel(
        const float4* __restrict__ agg4,
        const float* __restrict__ w1, const float* __restrict__ b1,
        const float* __restrict__ w2, const float* __restrict__ b2,
        float* __restrict__ out, int N) {
    constexpr int TR  = 128;
    constexpr int S   = 72;         // stride (floats), ==8 mod 32
    constexpr int IN_SZ = TR * S;
    constexpr int W_SZ  = 64 * S;

    extern __shared__ float sm[];
    float* in_s = sm;                      // [128][72]
    float* w1t  = sm + IN_SZ;              // [64][72]  transposed [n][k]
    float* hid  = sm;                      // overlays in_s
    float* w2t  = w1t + W_SZ;              // [64][72]  transposed [n][k]
    float* b1s  = w2t + W_SZ;
    float* b2s  = b1s + 64;

    int tid  = threadIdx.x;
    int row0 = blockIdx.x * TR;
    int nrows = N - row0; if (nrows > TR) nrows = TR;

    for (int i = tid; i < 64 * 64; i += 256) {
        int k = i >> 6, n = i & 63;
        w1t[n * S + k] = w1[i];
        w2t[n * S + k] = w2[i];
    }
    if (tid < 64) b1s[tid] = b1[tid];
    else if (tid < 128) b2s[tid - 64] = b2[tid - 64];

    for (int i = tid; i < TR * 16; i += 256) {
        int r = i >> 4, k4 = i & 15;
        float4 v = make_float4(0.f, 0.f, 0.f, 0.f);
        if (r < nrows) v = agg4[(size_t)(row0 + r) * 16 + k4];
        *(float4*)(in_s + r * S + k4 * 4) = v;
    }
    __syncthreads();

    const int wid  = tid >> 5;
    const int lane = tid & 31;
    const int g    = lane >> 2;
    const int tg   = lane & 3;
    const int m0   = wid * 16;

    float c1[8][4];
    #pragma unroll
    for (int j = 0; j < 8; j++) {
        int n0 = j * 8;
        float bv0 = b1s[n0 + 2 * tg], bv1 = b1s[n0 + 2 * tg + 1];
        c1[j][0] = bv0; c1[j][1] = bv1; c1[j][2] = bv0; c1[j][3] = bv1;
    }
    #pragma unroll
    for (int kk = 0; kk < 4; kk++) {
        int k0 = kk * 16;
        uint32_t ah[4], al[4];
        bf_split2(*(const float2*)(in_s + (m0 + g)     * S + k0 + 2 * tg),     ah[0], al[0]);
        bf_split2(*(const float2*)(in_s + (m0 + g + 8) * S + k0 + 2 * tg),     ah[1], al[1]);
        bf_split2(*(const float2*)(in_s + (m0 + g)     * S + k0 + 8 + 2 * tg), ah[2], al[2]);
        bf_split2(*(const float2*)(in_s + (m0 + g + 8) * S + k0 + 8 + 2 * tg), ah[3], al[3]);
        #pragma unroll
        for (int j = 0; j < 8; j++) {
            int n0 = j * 8;
            uint32_t bh0, bl0, bh1, bl1;
            bf_split2(*(const float2*)(w1t + (n0 + g) * S + k0 + 2 * tg),     bh0, bl0);
            bf_split2(*(const float2*)(w1t + (n0 + g) * S + k0 + 8 + 2 * tg), bh1, bl1);
            mma_bf16(c1[j], ah[0], ah[1], ah[2], ah[3], bh0, bh1);
            mma_bf16(c1[j], ah[0], ah[1], ah[2], ah[3], bl0, bl1);
            mma_bf16(c1[j], al[0], al[1], al[2], al[3], bh0, bh1);
        }
    }
    __syncthreads();

    #pragma unroll
    for (int j = 0; j < 8; j++) {
        int n0 = j * 8 + 2 * tg;
        *(float2*)(hid + (m0 + g)     * S + n0) =
            make_float2(fmaxf(c1[j][0], 0.f), fmaxf(c1[j][1], 0.f));
        *(float2*)(hid + (m0 + g + 8) * S + n0) =
            make_float2(fmaxf(c1[j][2], 0.f), fmaxf(c1[j][3], 0.f));
    }
    __syncthreads();

    {
        float c2[8][4];
        #pragma unroll
        for (int j = 0; j < 8; j++) {
            int n0 = j * 8;
            float bv0 = b2s[n0 + 2 * tg], bv1 = b2s[n0 + 2 * tg + 1];
            c2[j][0] = bv0; c2[j][1] = bv1; c2[j][2] = bv0; c2[j][3] = bv1;
        }
        #pragma unroll
        for (int kk = 0; kk < 4; kk++) {
            int k0 = kk * 16;
            uint32_t ah[4], al[4];
            bf_split2(*(const float2*)(hid + (m0 + g)     * S + k0 + 2 * tg),     ah[0], al[0]);
            bf_split2(*(const float2*)(hid + (m0 + g + 8) * S + k0 + 2 * tg),     ah[1], al[1]);
            bf_split2(*(const float2*)(hid + (m0 + g)     * S + k0 + 8 + 2 * tg), ah[2], al[2]);
            bf_split2(*(const float2*)(hid + (m0 + g + 8) * S + k0 + 8 + 2 * tg), ah[3], al[3]);
            #pragma unroll
            for (int j = 0; j < 8; j++) {
                int n0 = j * 8;
                uint32_t bh0, bl0, bh1, bl1;
                bf_split2(*(const float2*)(w2t + (n0 + g) * S + k0 + 2 * tg),     bh0, bl0);
                bf_split2(*(const float2*)(w2t + (n0 + g) * S + k0 + 8 + 2 * tg), bh1, bl1);
                mma_bf16(c2[j], ah[0], ah[1], ah[2], ah[3], bh0, bh1);
                mma_bf16(c2[j], ah[0], ah[1], ah[2], ah[3], bl0, bl1);
                mma_bf16(c2[j], al[0], al[1], al[2], al[3], bh0, bh1);
            }
        }
        int r0 = m0 + g, r1 = m0 + g + 8;
        #pragma unroll
        for (int j = 0; j < 8; j++) {
            int n0 = j * 8 + 2 * tg;
            if (r0 < nrows) {
                float2 v = make_float2(c2[j][0], c2[j][1]);
                if (RELU_OUT) { v.x = fmaxf(v.x, 0.f); v.y = fmaxf(v.y, 0.f); }
                *(float2*)(out + (size_t)(row0 + r0) * 64 + n0) = v;
            }
            if (r1 < nrows) {
                float2 v = make_float2(c2[j][2], c2[j][3]);
                if (RELU_OUT) { v.x = fmaxf(v.x, 0.f); v.y = fmaxf(v.y, 0.f); }
                *(float2*)(out + (size_t)(row0 + r1) * 64 + n0) = v;
            }
        }
    }
}

// ---------------------------------------------------------------------------
// BF16-split MLP for H=128, TR=64 (NEW): 256 threads, 8 warps; warp ->
// m-tile (wid>>1), n-half (wid&1). GEMM1 n=128 -> 8 n-tiles/warp (c1=32
// regs, no spill); GEMM2 K=128, n=64 -> 4 n-tiles/warp. Strides: in_s 72,
// hid 136, w2t 136 (all ==8 mod 32 -> aligned float2 fragment loads).
// hid[64][136]=8704 overlays in_s+w1t (4608+9216). Smem 90.9KB, 2 blocks/SM.
// ---------------------------------------------------------------------------
template<bool RELU_OUT>
__global__ void __launch_bounds__(256, 2) mlp_bf128_kernel(
        const float4* __restrict__ agg4,
        const float* __restrict__ w1, const float* __restrict__ b1,
        const float* __restrict__ w2, const float* __restrict__ b2,
        float* __restrict__ out, int N) {
    constexpr int TR  = 64;
    constexpr int H   = 128;
    constexpr int SA  = 72;          // in_s stride, ==8 mod 32
    constexpr int SH  = 136;         // hid stride, ==8 mod 32
    constexpr int SW2 = 136;         // w2t stride (k up to 128)
    constexpr int IN_SZ  = TR * SA;  // 4608
    constexpr int W1T_SZ = H * SA;   // 9216  (w1t[n][k], n=128, k=64)

    extern __shared__ float sm[];
    float* in_s = sm;                          // [64][72]
    float* w1t  = sm + IN_SZ;                  // [128][72] transposed [n][k]
    float* hid  = sm;                          // [64][136] overlays in+w1t
    float* w2t  = sm + IN_SZ + W1T_SZ;         // [64][136] transposed [n][k]
    float* b1s  = w2t + 64 * SW2;              // 128
    float* b2s  = b1s + H;                     // 64
    static_assert(TR * SH <= IN_SZ + W1T_SZ, "hid overlay must fit");

    int tid  = threadIdx.x;
    int row0 = blockIdx.x * TR;
    int nrows = N - row0; if (nrows > TR) nrows = TR;

    // Stage weights transposed: w1t[n*SA + k] = w1[k*128 + n] (k<64, n<128)
    for (int i = tid; i < 64 * H; i += 256) {
        int k = i >> 7, n = i & 127;
        w1t[n * SA + k] = w1[i];
    }
    // w2t[n*SW2 + h] = w2[h*64 + n] (h<128, n<64)
    for (int i = tid; i < H * 64; i += 256) {
        int h = i >> 6, n = i & 63;
        w2t[n * SW2 + h] = w2[i];
    }
    if (tid < H)  b1s[tid] = b1[tid];
    if (tid < 64) b2s[tid] = b2[tid];

    for (int i = tid; i < TR * 16; i += 256) {
        int r = i >> 4, k4 = i & 15;
        float4 v = make_float4(0.f, 0.f, 0.f, 0.f);
        if (r < nrows) v = agg4[(size_t)(row0 + r) * 16 + k4];
        *(float4*)(in_s + r * SA + k4 * 4) = v;
    }
    __syncthreads();

    const int wid  = tid >> 5;
    const int lane = tid & 31;
    const int g    = lane >> 2;
    const int tg   = lane & 3;
    const int m0   = (wid >> 1) * 16;   // 4 m-tiles x 16 rows
    const int nb1  = (wid & 1) * 64;    // GEMM1 n-half base

    // ---- GEMM1: hid = relu(in @ W1 + b1), K=64, n-half=64 (8 tiles) ----
    float c1[8][4];
    #pragma unroll
    for (int j = 0; j < 8; j++) {
        int n0 = nb1 + j * 8;
        float bv0 = b1s[n0 + 2 * tg], bv1 = b1s[n0 + 2 * tg + 1];
        c1[j][0] = bv0; c1[j][1] = bv1; c1[j][2] = bv0; c1[j][3] = bv1;
    }
    #pragma unroll
    for (int kk = 0; kk < 4; kk++) {
        int k0 = kk * 16;
        uint32_t ah[4], al[4];
        bf_split2(*(const float2*)(in_s + (m0 + g)     * SA + k0 + 2 * tg),     ah[0], al[0]);
        bf_split2(*(const float2*)(in_s + (m0 + g + 8) * SA + k0 + 2 * tg),     ah[1], al[1]);
        bf_split2(*(const float2*)(in_s + (m0 + g)     * SA + k0 + 8 + 2 * tg), ah[2], al[2]);
        bf_split2(*(const float2*)(in_s + (m0 + g + 8) * SA + k0 + 8 + 2 * tg), ah[3], al[3]);
        #pragma unroll
        for (int j = 0; j < 8; j++) {
            int n0 = nb1 + j * 8;
            uint32_t bh0, bl0, bh1, bl1;
            bf_split2(*(const float2*)(w1t + (n0 + g) * SA + k0 + 2 * tg),     bh0, bl0);
            bf_split2(*(const float2*)(w1t + (n0 + g) * SA + k0 + 8 + 2 * tg), bh1, bl1);
            mma_bf16(c1[j], ah[0], ah[1], ah[2], ah[3], bh0, bh1);
            mma_bf16(c1[j], ah[0], ah[1], ah[2], ah[3], bl0, bl1);
            mma_bf16(c1[j], al[0], al[1], al[2], al[3], bh0, bh1);
        }
    }
    __syncthreads();   // all reads of in_s / w1t done

    // Write relu(hid) [64][136]
    #pragma unroll
    for (int j = 0; j < 8; j++) {
        int n0 = nb1 + j * 8 + 2 * tg;
        *(float2*)(hid + (m0 + g)     * SH + n0) =
            make_float2(fmaxf(c1[j][0], 0.f), fmaxf(c1[j][1], 0.f));
        *(float2*)(hid + (m0 + g + 8) * SH + n0) =
            make_float2(fmaxf(c1[j][2], 0.f), fmaxf(c1[j][3], 0.f));
    }
    __syncthreads();

    // ---- GEMM2: out = hid @ W2 + b2, K=128 (8 k16-steps), n-half=32 ----
    {
        int nb2 = (wid & 1) * 32;
        float c2[4][4];
        #pragma unroll
        for (int j = 0; j < 4; j++) {
            int n0 = nb2 + j * 8;
            float bv0 = b2s[n0 + 2 * tg], bv1 = b2s[n0 + 2 * tg + 1];
            c2[j][0] = bv0; c2[j][1] = bv1; c2[j][2] = bv0; c2[j][3] = bv1;
        }
        #pragma unroll
        for (int kk = 0; kk < 8; kk++) {
            int k0 = kk * 16;
            uint32_t ah[4], al[4];
            bf_split2(*(const float2*)(hid + (m0 + g)     * SH + k0 + 2 * tg),     ah[0], al[0]);
            bf_split2(*(const float2*)(hid + (m0 + g + 8) * SH + k0 + 2 * tg),     ah[1], al[1]);
            bf_split2(*(const float2*)(hid + (m0 + g)     * SH + k0 + 8 + 2 * tg), ah[2], al[2]);
            bf_split2(*(const float2*)(hid + (m0 + g + 8) * SH + k0 + 8 + 2 * tg), ah[3], al[3]);
            #pragma unroll
            for (int j = 0; j < 4; j++) {
                int n0 = nb2 + j * 8;
                uint32_t bh0, bl0, bh1, bl1;
                bf_split2(*(const float2*)(w2t + (n0 + g) * SW2 + k0 + 2 * tg),     bh0, bl0);
                bf_split2(*(const float2*)(w2t + (n0 + g) * SW2 + k0 + 8 + 2 * tg), bh1, bl1);
                mma_bf16(c2[j], ah[0], ah[1], ah[2], ah[3], bh0, bh1);
                mma_bf16(c2[j], ah[0], ah[1], ah[2], ah[3], bl0, bl1);
                mma_bf16(c2[j], al[0], al[1], al[2], al[3], bh0, bh1);
            }
        }
        int r0 = m0 + g, r1 = m0 + g + 8;
        #pragma unroll
        for (int j = 0; j < 4; j++) {
            int n0 = nb2 + j * 8 + 2 * tg;
            if (r0 < nrows) {
                float2 v = make_float2(c2[j][0], c2[j][1]);
                if (RELU_OUT) { v.x = fmaxf(v.x, 0.f); v.y = fmaxf(v.y, 0.f); }
                *(float2*)(out + (size_t)(row0 + r0) * 64 + n0) = v;
            }
            if (r1 < nrows) {
                float2 v = make_float2(c2[j][2], c2[j][3]);
                if (RELU_OUT) { v.x = fmaxf(v.x, 0.f); v.y = fmaxf(v.y, 0.f); }
                *(float2*)(out + (size_t)(row0 + r1) * 64 + n0) = v;
            }
        }
    }
}

// ---------------------------------------------------------------------------
// Launch
// ---------------------------------------------------------------------------
static inline size_t smem_bf64() {
    return (size_t)(128 * 72 + 2 * 64 * 72 + 128) * sizeof(float);
}
static inline size_t smem_bf128() {
    // in(64*72) + w1t(128*72) + w2t(64*136) + b1(128) + b2(64)
    return (size_t)(64 * 72 + 128 * 72 + 64 * 136 + 128 + 64) * sizeof(float);
}

extern "C" void kernel_launch(void* const* d_in, const int* in_sizes, int n_in,
                              void* d_out, int out_size) {
    const float* x   = (const float*)d_in[0];
    const int*   ei  = (const int*)d_in[1];
    const float* ew  = (const float*)d_in[2];
    const float* w11 = (const float*)d_in[3];
    const float* b11 = (const float*)d_in[4];
    const float* w12 = (const float*)d_in[5];
    const float* b12 = (const float*)d_in[6];
    const float* w21 = (const float*)d_in[7];
    const float* b21 = (const float*)d_in[8];
    const float* w22 = (const float*)d_in[9];
    const float* b22 = (const float*)d_in[10];
    const float* w31 = (const float*)d_in[11];
    const float* b31 = (const float*)d_in[12];
    const float* w32 = (const float*)d_in[13];
    const float* b32 = (const float*)d_in[14];
    float* out = (float*)d_out;

    int N = in_sizes[0] / DIMF;
    int E = in_sizes[1] / 2;
    const int* src = ei;
    const int* dst = ei + E;

    float *agg, *h1, *h2;
    int *cnt, *rowptr, *cursor, *bsum;
    int2 *edata;
    cudaGetSymbolAddress((void**)&agg, g_agg);
    cudaGetSymbolAddress((void**)&h1, g_h1);
    cudaGetSymbolAddress((void**)&h2, g_h2);
    cudaGetSymbolAddress((void**)&cnt, g_cnt);
    cudaGetSymbolAddress((void**)&rowptr, g_rowptr);
    cudaGetSymbolAddress((void**)&cursor, g_cursor);
    cudaGetSymbolAddress((void**)&bsum, g_bsum);
    cudaGetSymbolAddress((void**)&edata, g_edata);

    size_t smB   = smem_bf64();
    size_t smB2  = smem_bf128();
    cudaFuncSetAttribute(mlp_bf64_kernel<true>,   cudaFuncAttributeMaxDynamicSharedMemorySize, (int)smB);
    cudaFuncSetAttribute(mlp_bf64_kernel<false>,  cudaFuncAttributeMaxDynamicSharedMemorySize, (int)smB);
    cudaFuncSetAttribute(mlp_bf128_kernel<true>,  cudaFuncAttributeMaxDynamicSharedMemorySize, (int)smB2);

    int NB = (N + 255) / 256;                // scan blocks (<=512 required)
    int eb = (E + 255) / 256;
    int gb = (N * 16 + 255) / 256;
    int mb64  = (N + 127) / 128;
    int mb128 = (N + 63) / 64;

    // --- CSR build (by destination) ---
    zero_cnt_kernel<<<NB, 256>>>(cnt, N);
    hist_kernel<<<eb, 256>>>(dst, cnt, E);
    scan_partial_kernel<<<NB, 256>>>(cnt, bsum, N);
    scan_top_kernel<<<1, 512>>>(bsum, NB);
    scan_final_kernel<<<NB + 1, 256>>>(cnt, bsum, rowptr, cursor, N);
    fill_kernel<<<eb, 256>>>(src, dst, ew, cursor, edata, E);

    // --- Layer 1: 64 -> 64 -> 64, relu (bf16-split, TR=128) ---
    gather_kernel<<<gb, 256>>>((const float4*)x, rowptr, edata, (float4*)agg, N);
    mlp_bf64_kernel<true><<<mb64, 256, smB>>>((const float4*)agg, w11, b11, w12, b12, h1, N);

    // --- Layer 2: 64 -> 128 -> 64, relu (bf16-split, TR=64) ---
    gather_kernel<<<gb, 256>>>((const float4*)h1, rowptr, edata, (float4*)agg, N);
    mlp_bf128_kernel<true><<<mb128, 256, smB2>>>((const float4*)agg, w21, b21, w22, b22, h2, N);

    // --- Layer 3: 64 -> 64 -> 64, no relu (bf16-split, TR=128) ---
    gather_kernel<<<gb, 256>>>((const float4*)h2, rowptr, edata, (float4*)agg, N);
    mlp_bf64_kernel<false><<<mb64, 256, smB>>>((const float4*)agg, w31, b31, w32, b32, out, N);
}